// round 10
// baseline (speedup 1.0000x reference)
#include <cuda_runtime.h>
#include <cuda_bf16.h>
#include <math.h>
#include <stdint.h>

#define EMBED 1024
#define HEADS 16
#define DK 64
#define SEQ 2048
#define MAXM 4096
#define NELEM (MAXM * EMBED)

// Persistent split-bf16 scratch (allocation-free rule: __device__ globals)
__device__ __nv_bfloat16 g_xh[NELEM], g_xl[NELEM];
__device__ __nv_bfloat16 g_wh[4 * EMBED * EMBED], g_wl[4 * EMBED * EMBED];
__device__ __nv_bfloat16 g_qh[NELEM], g_ql[NELEM];
__device__ __nv_bfloat16 g_kh[NELEM], g_kl[NELEM];
__device__ __nv_bfloat16 g_vh[NELEM], g_vl[NELEM];
__device__ __nv_bfloat16 g_ah[NELEM], g_al[NELEM];

// ===========================================================================
// Common helpers
// ===========================================================================
__device__ __forceinline__ uint32_t smem_u32(const void* p) {
    uint32_t a;
    asm("{ .reg .u64 t; cvta.to.shared.u64 t, %1; cvt.u32.u64 %0, t; }"
        : "=r"(a) : "l"(p));
    return a;
}

__device__ __forceinline__ void ldm_x4(uint32_t* r, uint32_t addr) {
    asm volatile("ldmatrix.sync.aligned.m8n8.x4.shared.b16 {%0,%1,%2,%3}, [%4];"
                 : "=r"(r[0]), "=r"(r[1]), "=r"(r[2]), "=r"(r[3]) : "r"(addr));
}

__device__ __forceinline__ void ldm_x4_t(uint32_t* r, uint32_t addr) {
    asm volatile("ldmatrix.sync.aligned.m8n8.x4.trans.shared.b16 {%0,%1,%2,%3}, [%4];"
                 : "=r"(r[0]), "=r"(r[1]), "=r"(r[2]), "=r"(r[3]) : "r"(addr));
}

__device__ __forceinline__ void mma16816(float* d, const uint32_t* a, const uint32_t* b) {
    asm volatile(
        "mma.sync.aligned.m16n8k16.row.col.f32.bf16.bf16.f32 "
        "{%0,%1,%2,%3}, {%4,%5,%6,%7}, {%8,%9}, {%0,%1,%2,%3};"
        : "+f"(d[0]), "+f"(d[1]), "+f"(d[2]), "+f"(d[3])
        : "r"(a[0]), "r"(a[1]), "r"(a[2]), "r"(a[3]), "r"(b[0]), "r"(b[1]));
}

__device__ __forceinline__ void cp_async16(uint32_t dst, const void* src) {
    asm volatile("cp.async.cg.shared.global [%0], [%1], 16;"
                 :: "r"(dst), "l"(src) : "memory");
}
#define CP_COMMIT() asm volatile("cp.async.commit_group;" ::: "memory")
#define CP_WAIT(N)  asm volatile("cp.async.wait_group %0;" :: "n"(N) : "memory")

__device__ __forceinline__ uint32_t packbf(__nv_bfloat16 a, __nv_bfloat16 b) {
    return (uint32_t)__bfloat16_as_ushort(a) | ((uint32_t)__bfloat16_as_ushort(b) << 16);
}

__device__ __forceinline__ void cvt_split4(float4 v, uint2& h, uint2& l) {
    __nv_bfloat16 h0 = __float2bfloat16(v.x);
    __nv_bfloat16 h1 = __float2bfloat16(v.y);
    __nv_bfloat16 h2 = __float2bfloat16(v.z);
    __nv_bfloat16 h3 = __float2bfloat16(v.w);
    __nv_bfloat16 l0 = __float2bfloat16(v.x - __bfloat162float(h0));
    __nv_bfloat16 l1 = __float2bfloat16(v.y - __bfloat162float(h1));
    __nv_bfloat16 l2 = __float2bfloat16(v.z - __bfloat162float(h2));
    __nv_bfloat16 l3 = __float2bfloat16(v.w - __bfloat162float(h3));
    h.x = packbf(h0, h1); h.y = packbf(h2, h3);
    l.x = packbf(l0, l1); l.y = packbf(l2, l3);
}

__device__ __forceinline__ void cvt_split2(float a, float b, uint32_t& h, uint32_t& l) {
    __nv_bfloat16 h0 = __float2bfloat16(a);
    __nv_bfloat16 h1 = __float2bfloat16(b);
    h = packbf(h0, h1);
    l = packbf(__float2bfloat16(a - __bfloat162float(h0)),
               __float2bfloat16(b - __bfloat162float(h1)));
}

// ===========================================================================
// Prep: split fp32 -> (hi, lo) bf16
// ===========================================================================
__global__ __launch_bounds__(256) void split_fp32_kernel(
    const float4* __restrict__ src, uint2* __restrict__ hi, uint2* __restrict__ lo, int n4)
{
    int i = blockIdx.x * blockDim.x + threadIdx.x;
    if (i < n4) {
        uint2 h, l;
        cvt_split4(src[i], h, l);
        hi[i] = h;
        lo[i] = l;
    }
}

__global__ __launch_bounds__(256) void split_w_kernel(
    const float4* __restrict__ w0, const float4* __restrict__ w1,
    const float4* __restrict__ w2, const float4* __restrict__ w3,
    uint2* __restrict__ hi, uint2* __restrict__ lo, int n4)
{
    const int z = blockIdx.y;
    const float4* src = (z == 0) ? w0 : (z == 1) ? w1 : (z == 2) ? w2 : w3;
    int i = blockIdx.x * blockDim.x + threadIdx.x;
    if (i < n4) {
        uint2 h, l;
        cvt_split4(src[i], h, l);
        hi[(size_t)z * n4 + i] = h;
        lo[(size_t)z * n4 + i] = l;
    }
}

// ===========================================================================
// GEMM on pre-split bf16:  C[m,n] = sum_k A[m,k]*B[n,k]  (NT)  — unchanged R9
// ===========================================================================
#define TM 128
#define TN 128
#define KCH 64
#define LDB 144
#define GT (128 * LDB)
#define GSTAGE (4 * GT)
#define NSTG 3
#define SMEM_GEMM (NSTG * GSTAGE)

template <int SPLIT_OUT>
__device__ __forceinline__ void gemm_bf16_body(
    const __nv_bfloat16* __restrict__ Ah, const __nv_bfloat16* __restrict__ Al,
    const __nv_bfloat16* __restrict__ Bh, const __nv_bfloat16* __restrict__ Bl,
    float* __restrict__ Cf,
    __nv_bfloat16* __restrict__ Ch, __nv_bfloat16* __restrict__ Cl,
    float scale)
{
    extern __shared__ char smem[];
    const uint32_t sbase = smem_u32(smem);
    const int tid  = threadIdx.x;
    const int lane = tid & 31;
    const int wid  = tid >> 5;
    const int wm   = wid & 3;
    const int wn   = wid >> 2;
    const int m0 = blockIdx.y * TM;
    const int n0 = blockIdx.x * TN;

    float acc[2][4][4];
#pragma unroll
    for (int i = 0; i < 2; i++)
#pragma unroll
        for (int j = 0; j < 4; j++)
#pragma unroll
            for (int r = 0; r < 4; r++) acc[i][j][r] = 0.0f;

    int lrow[2], lu4[2];
#pragma unroll
    for (int i = 0; i < 2; i++) {
        int idx = tid + i * 512;
        lrow[i] = idx >> 3;
        lu4[i]  = idx & 7;
    }

    const __nv_bfloat16* Abh = Ah + (size_t)m0 * EMBED;
    const __nv_bfloat16* Abl = Al + (size_t)m0 * EMBED;
    const __nv_bfloat16* Bbh = Bh + (size_t)n0 * EMBED;
    const __nv_bfloat16* Bbl = Bl + (size_t)n0 * EMBED;

    const int NCHUNK = EMBED / KCH;

    auto issue = [&](int c) {
        const uint32_t stu = sbase + (c % NSTG) * GSTAGE;
        const int koff = c * KCH;
#pragma unroll
        for (int i = 0; i < 2; i++) {
            size_t off = (size_t)lrow[i] * EMBED + koff + lu4[i] * 8;
            uint32_t bo = lrow[i] * LDB + lu4[i] * 16;
            cp_async16(stu + 0 * GT + bo, Abh + off);
            cp_async16(stu + 1 * GT + bo, Abl + off);
            cp_async16(stu + 2 * GT + bo, Bbh + off);
            cp_async16(stu + 3 * GT + bo, Bbl + off);
        }
    };

    issue(0); CP_COMMIT();
    issue(1); CP_COMMIT();

    const int a_row = wm * 32 + (lane & 15);
    const int a_kb  = (lane >> 4) * 16;
    const int b_row = wn * 32 + ((lane >> 4) & 1) * 8 + (lane & 7);
    const int b_kb  = ((lane >> 3) & 1) * 16;

    for (int c = 0; c < NCHUNK; ++c) {
        CP_WAIT(1);
        __syncthreads();
        if (c + 2 < NCHUNK) { issue(c + 2); CP_COMMIT(); }

        const int p = c % NSTG;
        const uint32_t sAh = sbase + p * GSTAGE;
        const uint32_t sAl = sAh + GT;
        const uint32_t sBh = sAh + 2 * GT;
        const uint32_t sBl = sAh + 3 * GT;

#pragma unroll
        for (int ks = 0; ks < 4; ++ks) {
            uint32_t ah[2][4], al[2][4];
            uint32_t bh[4][2], bl[4][2];

            const uint32_t akoff = ks * 32 + a_kb;
#pragma unroll
            for (int mi = 0; mi < 2; mi++) {
                uint32_t ro = (uint32_t)(a_row + mi * 16) * LDB + akoff;
                ldm_x4(ah[mi], sAh + ro);
                ldm_x4(al[mi], sAl + ro);
            }
            const uint32_t bkoff = ks * 32 + b_kb;
#pragma unroll
            for (int np = 0; np < 2; np++) {
                uint32_t ro = (uint32_t)(b_row + np * 16) * LDB + bkoff;
                uint32_t r[4];
                ldm_x4(r, sBh + ro);
                bh[np * 2][0] = r[0]; bh[np * 2][1] = r[1];
                bh[np * 2 + 1][0] = r[2]; bh[np * 2 + 1][1] = r[3];
                ldm_x4(r, sBl + ro);
                bl[np * 2][0] = r[0]; bl[np * 2][1] = r[1];
                bl[np * 2 + 1][0] = r[2]; bl[np * 2 + 1][1] = r[3];
            }

#pragma unroll
            for (int mi = 0; mi < 2; mi++)
#pragma unroll
                for (int ni = 0; ni < 4; ni++) {
                    mma16816(acc[mi][ni], ah[mi], bh[ni]);
                    mma16816(acc[mi][ni], ah[mi], bl[ni]);
                    mma16816(acc[mi][ni], al[mi], bh[ni]);
                }
        }
    }

    const int er = lane >> 2;
    const int ec = (lane & 3) * 2;
#pragma unroll
    for (int mi = 0; mi < 2; mi++) {
#pragma unroll
        for (int ni = 0; ni < 4; ni++) {
            int row = m0 + wm * 32 + mi * 16 + er;
            int col = n0 + wn * 32 + ni * 8 + ec;
            if (SPLIT_OUT) {
                float a0 = acc[mi][ni][0] * scale, a1 = acc[mi][ni][1] * scale;
                float a2 = acc[mi][ni][2] * scale, a3 = acc[mi][ni][3] * scale;
                uint32_t h, l;
                cvt_split2(a0, a1, h, l);
                *(uint32_t*)(Ch + (size_t)row * EMBED + col) = h;
                *(uint32_t*)(Cl + (size_t)row * EMBED + col) = l;
                cvt_split2(a2, a3, h, l);
                *(uint32_t*)(Ch + (size_t)(row + 8) * EMBED + col) = h;
                *(uint32_t*)(Cl + (size_t)(row + 8) * EMBED + col) = l;
            } else {
                *(float2*)(Cf + (size_t)row * EMBED + col) =
                    make_float2(acc[mi][ni][0], acc[mi][ni][1]);
                *(float2*)(Cf + (size_t)(row + 8) * EMBED + col) =
                    make_float2(acc[mi][ni][2], acc[mi][ni][3]);
            }
        }
    }
}

__global__ __launch_bounds__(512, 1) void qkv_tc_kernel()
{
    const int z = blockIdx.z;
    const __nv_bfloat16* Bh = g_wh + (size_t)z * EMBED * EMBED;
    const __nv_bfloat16* Bl = g_wl + (size_t)z * EMBED * EMBED;
    __nv_bfloat16 *Ch, *Cl;
    float scale;
    // Q scale folds 1/sqrt(DK) AND log2(e) so softmax can use exp2f.
    if (z == 0)      { Ch = g_qh; Cl = g_ql; scale = 0.125f * 1.4426950408889634f; }
    else if (z == 1) { Ch = g_kh; Cl = g_kl; scale = 1.0f; }
    else             { Ch = g_vh; Cl = g_vl; scale = 1.0f; }
    gemm_bf16_body<1>(g_xh, g_xl, Bh, Bl, nullptr, Ch, Cl, scale);
}

__global__ __launch_bounds__(512, 1) void out_tc_kernel(float* __restrict__ out)
{
    gemm_bf16_body<0>(g_ah, g_al,
                      g_wh + (size_t)3 * EMBED * EMBED, g_wl + (size_t)3 * EMBED * EMBED,
                      out, nullptr, nullptr, 1.0f);
}

// ===========================================================================
// Tensor-core flash attention, 256 threads = 8 warps, 2 CTAs/SM.
// CTA = 128 query rows; 64-key chunks; 3-stage cp.async ring where the
// 3rd stage initially holds Q (dead after fragments are pulled).
// Softmax in base-2 domain (Q pre-scaled by log2e/8) -> exp2f.
// ===========================================================================
#define KT (64 * LDB)                  // 9216
#define KVST (4 * KT)                  // 36864 per stage (Kh Kl Vh Vl)
#define SMEM_ATTN (3 * KVST)           // 110592 -> 2 CTAs/SM

__global__ __launch_bounds__(256, 2) void attn_tc_kernel(
    const float* __restrict__ qw)
{
    extern __shared__ char smem[];
    const uint32_t sb = smem_u32(smem);
    const int tid  = threadIdx.x;
    const int lane = tid & 31;
    const int w    = tid >> 5;        // warp 0..7 -> q rows w*16..
    const int h = blockIdx.y;
    const int b = blockIdx.z;
    const int q0 = blockIdx.x * 128;

    const size_t base = (size_t)b * SEQ * EMBED + (size_t)h * DK;

    // K/V cp.async slots: 64 rows x 8 uint4 = 512 per component / 256 thr = 2
    int krow[2], ku4[2];
#pragma unroll
    for (int i = 0; i < 2; i++) {
        int idx = i * 256 + tid;
        krow[i] = idx >> 3;
        ku4[i]  = idx & 7;
    }

    auto issue_kv = [&](int c) {
        const uint32_t stu = sb + (c % 3) * KVST;
#pragma unroll
        for (int i = 0; i < 2; i++) {
            size_t off = base + (size_t)(c * 64 + krow[i]) * EMBED + ku4[i] * 8;
            uint32_t bo = krow[i] * LDB + ku4[i] * 16;
            cp_async16(stu + 0 * KT + bo, g_kh + off);
            cp_async16(stu + 1 * KT + bo, g_kl + off);
            cp_async16(stu + 2 * KT + bo, g_vh + off);
            cp_async16(stu + 3 * KT + bo, g_vl + off);
        }
    };

    issue_kv(0); CP_COMMIT();
    issue_kv(1); CP_COMMIT();

    // ---- stage Q (128 rows, hi+lo) into stage-2 region while K/V fly ----
    {
        const __nv_bfloat16* Qh = g_qh + base + (size_t)q0 * EMBED;
        const __nv_bfloat16* Ql = g_ql + base + (size_t)q0 * EMBED;
        char* qdst = smem + 2 * KVST;
#pragma unroll
        for (int i = 0; i < 4; i++) {
            int idx = i * 256 + tid;          // 0..1023
            int row = idx >> 3, u4 = idx & 7;
            size_t off = (size_t)row * EMBED + u4 * 8;
            uint32_t bo = row * LDB + u4 * 16;
            *(uint4*)(qdst + bo) = *(const uint4*)(Qh + off);
            *(uint4*)(qdst + 2 * KT + bo) = *(const uint4*)(Ql + off);
        }
    }
    __syncthreads();

    // ---- Q fragments, register resident ----
    uint32_t qh[4][4], ql[4][4];
    {
        const uint32_t qbase = sb + 2 * KVST;
        const uint32_t aoff = (uint32_t)(w * 16 + (lane & 15)) * LDB + (lane >> 4) * 16;
#pragma unroll
        for (int ks = 0; ks < 4; ks++) {
            ldm_x4(qh[ks], qbase + aoff + ks * 32);
            ldm_x4(ql[ks], qbase + 2 * KT + aoff + ks * 32);
        }
    }
    __syncthreads();   // all warps done reading Q before stage 2 is reused

    float O[8][4];
#pragma unroll
    for (int i = 0; i < 8; i++)
#pragma unroll
        for (int j = 0; j < 4; j++) O[i][j] = 0.0f;
    float M0 = -1e30f, M1 = -1e30f, L0 = 0.0f, L1 = 0.0f;

    const uint32_t kb_row = ((lane >> 4) & 1) * 8 + (lane & 7);
    const uint32_t kb_kb  = ((lane >> 3) & 1) * 16;
    const uint32_t vb_row = ((lane >> 3) & 1) * 8 + (lane & 7);
    const uint32_t vb_nb  = (lane >> 4) * 16;

    const int NCH = SEQ / 64;   // 32
    for (int c = 0; c < NCH; ++c) {
        CP_WAIT(1);
        __syncthreads();
        if (c + 2 < NCH) { issue_kv(c + 2); CP_COMMIT(); }

        const int p = c % 3;
        const uint32_t sKh = sb + p * KVST;
        const uint32_t sKl = sKh + KT;
        const uint32_t sVh = sKh + 2 * KT;
        const uint32_t sVl = sKh + 3 * KT;

        // ---- scores (base-2 domain; Q pre-scaled by log2e/8) ----
        float s[8][4];
#pragma unroll
        for (int i = 0; i < 8; i++)
#pragma unroll
            for (int j = 0; j < 4; j++) s[i][j] = 0.0f;

#pragma unroll
        for (int ks = 0; ks < 4; ks++) {
#pragma unroll
            for (int kp = 0; kp < 4; kp++) {
                uint32_t ro = (uint32_t)(kp * 16 + kb_row) * LDB + kb_kb + ks * 32;
                uint32_t rh[4], rl[4];
                ldm_x4(rh, sKh + ro);
                ldm_x4(rl, sKl + ro);
                uint32_t bh0[2] = { rh[0], rh[1] }, bh1[2] = { rh[2], rh[3] };
                uint32_t bl0[2] = { rl[0], rl[1] }, bl1[2] = { rl[2], rl[3] };
                mma16816(s[2 * kp],     qh[ks], bh0);
                mma16816(s[2 * kp],     qh[ks], bl0);
                mma16816(s[2 * kp],     ql[ks], bh0);
                mma16816(s[2 * kp + 1], qh[ks], bh1);
                mma16816(s[2 * kp + 1], qh[ks], bl1);
                mma16816(s[2 * kp + 1], ql[ks], bh1);
            }
        }

        // ---- online softmax (base 2) ----
        float rm0 = -1e30f, rm1 = -1e30f;
#pragma unroll
        for (int i = 0; i < 8; i++) {
            rm0 = fmaxf(rm0, fmaxf(s[i][0], s[i][1]));
            rm1 = fmaxf(rm1, fmaxf(s[i][2], s[i][3]));
        }
        rm0 = fmaxf(rm0, __shfl_xor_sync(0xFFFFFFFF, rm0, 1));
        rm0 = fmaxf(rm0, __shfl_xor_sync(0xFFFFFFFF, rm0, 2));
        rm1 = fmaxf(rm1, __shfl_xor_sync(0xFFFFFFFF, rm1, 1));
        rm1 = fmaxf(rm1, __shfl_xor_sync(0xFFFFFFFF, rm1, 2));

        float Mn0 = fmaxf(M0, rm0), Mn1 = fmaxf(M1, rm1);
        float sc0 = exp2f(M0 - Mn0), sc1 = exp2f(M1 - Mn1);
        M0 = Mn0; M1 = Mn1;
        L0 *= sc0; L1 *= sc1;
#pragma unroll
        for (int i = 0; i < 8; i++) {
            O[i][0] *= sc0; O[i][1] *= sc0;
            O[i][2] *= sc1; O[i][3] *= sc1;
        }
#pragma unroll
        for (int i = 0; i < 8; i++) {
            s[i][0] = exp2f(s[i][0] - M0);
            s[i][1] = exp2f(s[i][1] - M0);
            s[i][2] = exp2f(s[i][2] - M1);
            s[i][3] = exp2f(s[i][3] - M1);
            L0 += s[i][0] + s[i][1];
            L1 += s[i][2] + s[i][3];
        }

        // ---- O += P . V ----
#pragma unroll
        for (int ks = 0; ks < 4; ks++) {
            uint32_t ph[4], pl[4];
            cvt_split2(s[2 * ks][0],     s[2 * ks][1],     ph[0], pl[0]);
            cvt_split2(s[2 * ks][2],     s[2 * ks][3],     ph[1], pl[1]);
            cvt_split2(s[2 * ks + 1][0], s[2 * ks + 1][1], ph[2], pl[2]);
            cvt_split2(s[2 * ks + 1][2], s[2 * ks + 1][3], ph[3], pl[3]);

            const uint32_t vro = (uint32_t)(ks * 16 + vb_row) * LDB + vb_nb;
#pragma unroll
            for (int ntp = 0; ntp < 4; ntp++) {
                uint32_t rh[4], rl[4];
                ldm_x4_t(rh, sVh + vro + ntp * 32);
                ldm_x4_t(rl, sVl + vro + ntp * 32);
                uint32_t vh0[2] = { rh[0], rh[1] }, vh1[2] = { rh[2], rh[3] };
                uint32_t vl0[2] = { rl[0], rl[1] }, vl1[2] = { rl[2], rl[3] };
                mma16816(O[2 * ntp],     ph, vh0);
                mma16816(O[2 * ntp],     ph, vl0);
                mma16816(O[2 * ntp],     pl, vh0);
                mma16816(O[2 * ntp + 1], ph, vh1);
                mma16816(O[2 * ntp + 1], ph, vl1);
                mma16816(O[2 * ntp + 1], pl, vh1);
            }
        }
    }

    // ---- finalize: normalize, sin-mix, write split bf16 ----
    L0 += __shfl_xor_sync(0xFFFFFFFF, L0, 1);
    L0 += __shfl_xor_sync(0xFFFFFFFF, L0, 2);
    L1 += __shfl_xor_sync(0xFFFFFFFF, L1, 1);
    L1 += __shfl_xor_sync(0xFFFFFFFF, L1, 2);
    const float inv0 = 1.0f / L0, inv1 = 1.0f / L1;
    const float wmix = 1.0f / (1.0f + __expf(-qw[h]));

    const int r0 = q0 + w * 16 + (lane >> 2);
    const int c0 = (lane & 3) * 2;
    __nv_bfloat16* oh0 = g_ah + base + (size_t)r0 * EMBED + c0;
    __nv_bfloat16* ol0 = g_al + base + (size_t)r0 * EMBED + c0;
    __nv_bfloat16* oh1 = g_ah + base + (size_t)(r0 + 8) * EMBED + c0;
    __nv_bfloat16* ol1 = g_al + base + (size_t)(r0 + 8) * EMBED + c0;
#pragma unroll
    for (int nt = 0; nt < 8; nt++) {
        float ca = O[nt][0] * inv0, cb = O[nt][1] * inv0;
        float cc = O[nt][2] * inv1, cd = O[nt][3] * inv1;
        float ma = wmix * sinf(ca) + (1.0f - wmix) * ca;
        float mb = wmix * sinf(cb) + (1.0f - wmix) * cb;
        float mc = wmix * sinf(cc) + (1.0f - wmix) * cc;
        float md = wmix * sinf(cd) + (1.0f - wmix) * cd;
        uint32_t hh, ll;
        cvt_split2(ma, mb, hh, ll);
        *(uint32_t*)(oh0 + nt * 8) = hh;
        *(uint32_t*)(ol0 + nt * 8) = ll;
        cvt_split2(mc, md, hh, ll);
        *(uint32_t*)(oh1 + nt * 8) = hh;
        *(uint32_t*)(ol1 + nt * 8) = ll;
    }
}

// ---------------------------------------------------------------------------
extern "C" void kernel_launch(void* const* d_in, const int* in_sizes, int n_in,
                              void* d_out, int out_size)
{
    const float* x  = (const float*)d_in[0];
    const float* Wq = (const float*)d_in[1];
    const float* Wk = (const float*)d_in[2];
    const float* Wv = (const float*)d_in[3];
    const float* Wo = (const float*)d_in[4];
    const float* qw = (const float*)d_in[5];
    float* out = (float*)d_out;

    const int M = in_sizes[0] / EMBED;   // B*S = 4096
    const int S = SEQ;
    const int B = M / S;

    static bool attr_done = false;
    if (!attr_done) {
        cudaFuncSetAttribute(qkv_tc_kernel, cudaFuncAttributeMaxDynamicSharedMemorySize, SMEM_GEMM);
        cudaFuncSetAttribute(out_tc_kernel, cudaFuncAttributeMaxDynamicSharedMemorySize, SMEM_GEMM);
        cudaFuncSetAttribute(attn_tc_kernel, cudaFuncAttributeMaxDynamicSharedMemorySize, SMEM_ATTN);
        attr_done = true;
    }

    __nv_bfloat16 *p_xh, *p_xl, *p_wh, *p_wl;
    cudaGetSymbolAddress((void**)&p_xh, g_xh);
    cudaGetSymbolAddress((void**)&p_xl, g_xl);
    cudaGetSymbolAddress((void**)&p_wh, g_wh);
    cudaGetSymbolAddress((void**)&p_wl, g_wl);

    // 0) Split x and weights into persistent hi/lo bf16
    {
        const int n4x = M * EMBED / 4;
        split_fp32_kernel<<<(n4x + 255) / 256, 256>>>(
            (const float4*)x, (uint2*)p_xh, (uint2*)p_xl, n4x);
        const int n4w = EMBED * EMBED / 4;
        dim3 gw((n4w + 255) / 256, 4);
        split_w_kernel<<<gw, 256>>>(
            (const float4*)Wq, (const float4*)Wk, (const float4*)Wv, (const float4*)Wo,
            (uint2*)p_wh, (uint2*)p_wl, n4w);
    }

    // 1) Q,K,V projections (Q pre-scaled by log2e/8)
    {
        dim3 grid(EMBED / TN, M / TM, 3);
        qkv_tc_kernel<<<grid, 512, SMEM_GEMM>>>();
    }
    // 2) Flash attention (2 CTAs/SM, desynchronized) + sin-mix epilogue
    {
        dim3 grid(S / 128, HEADS, B);
        attn_tc_kernel<<<grid, 256, SMEM_ATTN>>>(qw);
    }
    // 3) Output projection -> fp32 d_out
    {
        dim3 grid(EMBED / TN, M / TM, 1);
        out_tc_kernel<<<grid, 512, SMEM_GEMM>>>(out);
    }
}

// round 11
// speedup vs baseline: 1.0493x; 1.0493x over previous
#include <cuda_runtime.h>
#include <cuda_bf16.h>
#include <math.h>
#include <stdint.h>

#define EMBED 1024
#define HEADS 16
#define DK 64
#define SEQ 2048
#define MAXM 4096
#define NELEM (MAXM * EMBED)

// Persistent split-bf16 scratch (allocation-free rule: __device__ globals)
__device__ __nv_bfloat16 g_xh[NELEM], g_xl[NELEM];
__device__ __nv_bfloat16 g_wh[4 * EMBED * EMBED], g_wl[4 * EMBED * EMBED];
__device__ __nv_bfloat16 g_qh[NELEM], g_ql[NELEM];
__device__ __nv_bfloat16 g_kh[NELEM], g_kl[NELEM];
__device__ __nv_bfloat16 g_vh[NELEM], g_vl[NELEM];
__device__ __nv_bfloat16 g_ah[NELEM], g_al[NELEM];

// ===========================================================================
// Common helpers
// ===========================================================================
__device__ __forceinline__ uint32_t smem_u32(const void* p) {
    uint32_t a;
    asm("{ .reg .u64 t; cvta.to.shared.u64 t, %1; cvt.u32.u64 %0, t; }"
        : "=r"(a) : "l"(p));
    return a;
}

__device__ __forceinline__ void ldm_x4(uint32_t* r, uint32_t addr) {
    asm volatile("ldmatrix.sync.aligned.m8n8.x4.shared.b16 {%0,%1,%2,%3}, [%4];"
                 : "=r"(r[0]), "=r"(r[1]), "=r"(r[2]), "=r"(r[3]) : "r"(addr));
}

__device__ __forceinline__ void ldm_x4_t(uint32_t* r, uint32_t addr) {
    asm volatile("ldmatrix.sync.aligned.m8n8.x4.trans.shared.b16 {%0,%1,%2,%3}, [%4];"
                 : "=r"(r[0]), "=r"(r[1]), "=r"(r[2]), "=r"(r[3]) : "r"(addr));
}

__device__ __forceinline__ void mma16816(float* d, const uint32_t* a, const uint32_t* b) {
    asm volatile(
        "mma.sync.aligned.m16n8k16.row.col.f32.bf16.bf16.f32 "
        "{%0,%1,%2,%3}, {%4,%5,%6,%7}, {%8,%9}, {%0,%1,%2,%3};"
        : "+f"(d[0]), "+f"(d[1]), "+f"(d[2]), "+f"(d[3])
        : "r"(a[0]), "r"(a[1]), "r"(a[2]), "r"(a[3]), "r"(b[0]), "r"(b[1]));
}

__device__ __forceinline__ void cp_async16(uint32_t dst, const void* src) {
    asm volatile("cp.async.cg.shared.global [%0], [%1], 16;"
                 :: "r"(dst), "l"(src) : "memory");
}
#define CP_COMMIT() asm volatile("cp.async.commit_group;" ::: "memory")
#define CP_WAIT(N)  asm volatile("cp.async.wait_group %0;" :: "n"(N) : "memory")

__device__ __forceinline__ uint32_t packbf(__nv_bfloat16 a, __nv_bfloat16 b) {
    return (uint32_t)__bfloat16_as_ushort(a) | ((uint32_t)__bfloat16_as_ushort(b) << 16);
}

__device__ __forceinline__ void cvt_split4(float4 v, uint2& h, uint2& l) {
    __nv_bfloat16 h0 = __float2bfloat16(v.x);
    __nv_bfloat16 h1 = __float2bfloat16(v.y);
    __nv_bfloat16 h2 = __float2bfloat16(v.z);
    __nv_bfloat16 h3 = __float2bfloat16(v.w);
    __nv_bfloat16 l0 = __float2bfloat16(v.x - __bfloat162float(h0));
    __nv_bfloat16 l1 = __float2bfloat16(v.y - __bfloat162float(h1));
    __nv_bfloat16 l2 = __float2bfloat16(v.z - __bfloat162float(h2));
    __nv_bfloat16 l3 = __float2bfloat16(v.w - __bfloat162float(h3));
    h.x = packbf(h0, h1); h.y = packbf(h2, h3);
    l.x = packbf(l0, l1); l.y = packbf(l2, l3);
}

__device__ __forceinline__ void cvt_split2(float a, float b, uint32_t& h, uint32_t& l) {
    __nv_bfloat16 h0 = __float2bfloat16(a);
    __nv_bfloat16 h1 = __float2bfloat16(b);
    h = packbf(h0, h1);
    l = packbf(__float2bfloat16(a - __bfloat162float(h0)),
               __float2bfloat16(b - __bfloat162float(h1)));
}

// ===========================================================================
// Prep: split fp32 -> (hi, lo) bf16
// ===========================================================================
__global__ __launch_bounds__(256) void split_fp32_kernel(
    const float4* __restrict__ src, uint2* __restrict__ hi, uint2* __restrict__ lo, int n4)
{
    int i = blockIdx.x * blockDim.x + threadIdx.x;
    if (i < n4) {
        uint2 h, l;
        cvt_split4(src[i], h, l);
        hi[i] = h;
        lo[i] = l;
    }
}

__global__ __launch_bounds__(256) void split_w_kernel(
    const float4* __restrict__ w0, const float4* __restrict__ w1,
    const float4* __restrict__ w2, const float4* __restrict__ w3,
    uint2* __restrict__ hi, uint2* __restrict__ lo, int n4)
{
    const int z = blockIdx.y;
    const float4* src = (z == 0) ? w0 : (z == 1) ? w1 : (z == 2) ? w2 : w3;
    int i = blockIdx.x * blockDim.x + threadIdx.x;
    if (i < n4) {
        uint2 h, l;
        cvt_split4(src[i], h, l);
        hi[(size_t)z * n4 + i] = h;
        lo[(size_t)z * n4 + i] = l;
    }
}

// ===========================================================================
// GEMM on pre-split bf16 (unchanged from R9)
// ===========================================================================
#define TM 128
#define TN 128
#define KCH 64
#define LDB 144
#define GT (128 * LDB)
#define GSTAGE (4 * GT)
#define NSTG 3
#define SMEM_GEMM (NSTG * GSTAGE)

template <int SPLIT_OUT>
__device__ __forceinline__ void gemm_bf16_body(
    const __nv_bfloat16* __restrict__ Ah, const __nv_bfloat16* __restrict__ Al,
    const __nv_bfloat16* __restrict__ Bh, const __nv_bfloat16* __restrict__ Bl,
    float* __restrict__ Cf,
    __nv_bfloat16* __restrict__ Ch, __nv_bfloat16* __restrict__ Cl,
    float scale)
{
    extern __shared__ char smem[];
    const uint32_t sbase = smem_u32(smem);
    const int tid  = threadIdx.x;
    const int lane = tid & 31;
    const int wid  = tid >> 5;
    const int wm   = wid & 3;
    const int wn   = wid >> 2;
    const int m0 = blockIdx.y * TM;
    const int n0 = blockIdx.x * TN;

    float acc[2][4][4];
#pragma unroll
    for (int i = 0; i < 2; i++)
#pragma unroll
        for (int j = 0; j < 4; j++)
#pragma unroll
            for (int r = 0; r < 4; r++) acc[i][j][r] = 0.0f;

    int lrow[2], lu4[2];
#pragma unroll
    for (int i = 0; i < 2; i++) {
        int idx = tid + i * 512;
        lrow[i] = idx >> 3;
        lu4[i]  = idx & 7;
    }

    const __nv_bfloat16* Abh = Ah + (size_t)m0 * EMBED;
    const __nv_bfloat16* Abl = Al + (size_t)m0 * EMBED;
    const __nv_bfloat16* Bbh = Bh + (size_t)n0 * EMBED;
    const __nv_bfloat16* Bbl = Bl + (size_t)n0 * EMBED;

    const int NCHUNK = EMBED / KCH;

    auto issue = [&](int c) {
        const uint32_t stu = sbase + (c % NSTG) * GSTAGE;
        const int koff = c * KCH;
#pragma unroll
        for (int i = 0; i < 2; i++) {
            size_t off = (size_t)lrow[i] * EMBED + koff + lu4[i] * 8;
            uint32_t bo = lrow[i] * LDB + lu4[i] * 16;
            cp_async16(stu + 0 * GT + bo, Abh + off);
            cp_async16(stu + 1 * GT + bo, Abl + off);
            cp_async16(stu + 2 * GT + bo, Bbh + off);
            cp_async16(stu + 3 * GT + bo, Bbl + off);
        }
    };

    issue(0); CP_COMMIT();
    issue(1); CP_COMMIT();

    const int a_row = wm * 32 + (lane & 15);
    const int a_kb  = (lane >> 4) * 16;
    const int b_row = wn * 32 + ((lane >> 4) & 1) * 8 + (lane & 7);
    const int b_kb  = ((lane >> 3) & 1) * 16;

    for (int c = 0; c < NCHUNK; ++c) {
        CP_WAIT(1);
        __syncthreads();
        if (c + 2 < NCHUNK) { issue(c + 2); CP_COMMIT(); }

        const int p = c % NSTG;
        const uint32_t sAh = sbase + p * GSTAGE;
        const uint32_t sAl = sAh + GT;
        const uint32_t sBh = sAh + 2 * GT;
        const uint32_t sBl = sAh + 3 * GT;

#pragma unroll
        for (int ks = 0; ks < 4; ++ks) {
            uint32_t ah[2][4], al[2][4];
            uint32_t bh[4][2], bl[4][2];

            const uint32_t akoff = ks * 32 + a_kb;
#pragma unroll
            for (int mi = 0; mi < 2; mi++) {
                uint32_t ro = (uint32_t)(a_row + mi * 16) * LDB + akoff;
                ldm_x4(ah[mi], sAh + ro);
                ldm_x4(al[mi], sAl + ro);
            }
            const uint32_t bkoff = ks * 32 + b_kb;
#pragma unroll
            for (int np = 0; np < 2; np++) {
                uint32_t ro = (uint32_t)(b_row + np * 16) * LDB + bkoff;
                uint32_t r[4];
                ldm_x4(r, sBh + ro);
                bh[np * 2][0] = r[0]; bh[np * 2][1] = r[1];
                bh[np * 2 + 1][0] = r[2]; bh[np * 2 + 1][1] = r[3];
                ldm_x4(r, sBl + ro);
                bl[np * 2][0] = r[0]; bl[np * 2][1] = r[1];
                bl[np * 2 + 1][0] = r[2]; bl[np * 2 + 1][1] = r[3];
            }

#pragma unroll
            for (int mi = 0; mi < 2; mi++)
#pragma unroll
                for (int ni = 0; ni < 4; ni++) {
                    mma16816(acc[mi][ni], ah[mi], bh[ni]);
                    mma16816(acc[mi][ni], ah[mi], bl[ni]);
                    mma16816(acc[mi][ni], al[mi], bh[ni]);
                }
        }
    }

    const int er = lane >> 2;
    const int ec = (lane & 3) * 2;
#pragma unroll
    for (int mi = 0; mi < 2; mi++) {
#pragma unroll
        for (int ni = 0; ni < 4; ni++) {
            int row = m0 + wm * 32 + mi * 16 + er;
            int col = n0 + wn * 32 + ni * 8 + ec;
            if (SPLIT_OUT) {
                float a0 = acc[mi][ni][0] * scale, a1 = acc[mi][ni][1] * scale;
                float a2 = acc[mi][ni][2] * scale, a3 = acc[mi][ni][3] * scale;
                uint32_t h, l;
                cvt_split2(a0, a1, h, l);
                *(uint32_t*)(Ch + (size_t)row * EMBED + col) = h;
                *(uint32_t*)(Cl + (size_t)row * EMBED + col) = l;
                cvt_split2(a2, a3, h, l);
                *(uint32_t*)(Ch + (size_t)(row + 8) * EMBED + col) = h;
                *(uint32_t*)(Cl + (size_t)(row + 8) * EMBED + col) = l;
            } else {
                *(float2*)(Cf + (size_t)row * EMBED + col) =
                    make_float2(acc[mi][ni][0], acc[mi][ni][1]);
                *(float2*)(Cf + (size_t)(row + 8) * EMBED + col) =
                    make_float2(acc[mi][ni][2], acc[mi][ni][3]);
            }
        }
    }
}

__global__ __launch_bounds__(512, 1) void qkv_tc_kernel()
{
    const int z = blockIdx.z;
    const __nv_bfloat16* Bh = g_wh + (size_t)z * EMBED * EMBED;
    const __nv_bfloat16* Bl = g_wl + (size_t)z * EMBED * EMBED;
    __nv_bfloat16 *Ch, *Cl;
    float scale;
    // Q scale folds 1/sqrt(DK) AND log2(e) so softmax is in base-2 domain.
    if (z == 0)      { Ch = g_qh; Cl = g_ql; scale = 0.125f * 1.4426950408889634f; }
    else if (z == 1) { Ch = g_kh; Cl = g_kl; scale = 1.0f; }
    else             { Ch = g_vh; Cl = g_vl; scale = 1.0f; }
    gemm_bf16_body<1>(g_xh, g_xl, Bh, Bl, nullptr, Ch, Cl, scale);
}

__global__ __launch_bounds__(512, 1) void out_tc_kernel(float* __restrict__ out)
{
    gemm_bf16_body<0>(g_ah, g_al,
                      g_wh + (size_t)3 * EMBED * EMBED, g_wl + (size_t)3 * EMBED * EMBED,
                      out, nullptr, nullptr, 1.0f);
}

// ===========================================================================
// Tensor-core flash attention, 512 threads = 16 warps, 256 q-rows (R9 shape).
// SHIFT-FREE softmax: P = exp2(s), L = sum P, normalize at end.
// (s in base-2 domain is statistically bounded |s| < ~12; fp32 exponent
//  range makes the max-subtraction unnecessary -> no shfl/max/rescale in loop.)
// ===========================================================================
#define KT (64 * LDB)                  // 9216
#define QT (256 * LDB)                 // 36864
#define AQH 0
#define AQL QT
#define AKV (2 * QT)
#define KVST (4 * KT)                  // Kh Kl Vh Vl per stage = 36864
#define SMEM_ATTN (2 * QT + NSTG * KVST)  // 184320

__global__ __launch_bounds__(512, 1) void attn_tc_kernel(
    const float* __restrict__ qw)
{
    extern __shared__ char smem[];
    const uint32_t sb = smem_u32(smem);
    const int tid  = threadIdx.x;
    const int lane = tid & 31;
    const int w    = tid >> 5;
    const int h = blockIdx.y;
    const int b = blockIdx.z;
    const int q0 = blockIdx.x * 256;

    const size_t base = (size_t)b * SEQ * EMBED + (size_t)h * DK;

    const int krow = tid >> 3;
    const int ku4  = tid & 7;

    auto issue_kv = [&](int c) {
        const uint32_t stu = sb + AKV + (c % NSTG) * KVST;
        size_t off = base + (size_t)(c * 64 + krow) * EMBED + ku4 * 8;
        uint32_t bo = krow * LDB + ku4 * 16;
        cp_async16(stu + 0 * KT + bo, g_kh + off);
        cp_async16(stu + 1 * KT + bo, g_kl + off);
        cp_async16(stu + 2 * KT + bo, g_vh + off);
        cp_async16(stu + 3 * KT + bo, g_vl + off);
    };

    issue_kv(0); CP_COMMIT();
    issue_kv(1); CP_COMMIT();

    // ---- copy pre-split Q tile into SMEM ----
    {
        const __nv_bfloat16* Qh = g_qh + base + (size_t)q0 * EMBED;
        const __nv_bfloat16* Ql = g_ql + base + (size_t)q0 * EMBED;
#pragma unroll
        for (int i = 0; i < 4; i++) {
            int idx = i * 512 + tid;
            int row = idx >> 3, u4 = idx & 7;
            size_t off = (size_t)row * EMBED + u4 * 8;
            uint32_t bo = row * LDB + u4 * 16;
            *(uint4*)(smem + AQH + bo) = *(const uint4*)(Qh + off);
            *(uint4*)(smem + AQL + bo) = *(const uint4*)(Ql + off);
        }
    }
    __syncthreads();

    // ---- Q fragments, register resident ----
    uint32_t qh[4][4], ql[4][4];
    {
        const uint32_t aoff = (uint32_t)(w * 16 + (lane & 15)) * LDB + (lane >> 4) * 16;
#pragma unroll
        for (int ks = 0; ks < 4; ks++) {
            ldm_x4(qh[ks], sb + AQH + aoff + ks * 32);
            ldm_x4(ql[ks], sb + AQL + aoff + ks * 32);
        }
    }

    float O[8][4];
#pragma unroll
    for (int i = 0; i < 8; i++)
#pragma unroll
        for (int j = 0; j < 4; j++) O[i][j] = 0.0f;
    // 4 independent L accumulators per row-group to shorten add chains
    float L0a = 0.0f, L0b = 0.0f, L1a = 0.0f, L1b = 0.0f;

    const uint32_t kb_row = ((lane >> 4) & 1) * 8 + (lane & 7);
    const uint32_t kb_kb  = ((lane >> 3) & 1) * 16;
    const uint32_t vb_row = ((lane >> 3) & 1) * 8 + (lane & 7);
    const uint32_t vb_nb  = (lane >> 4) * 16;

    const int NCH = SEQ / 64;   // 32
    for (int c = 0; c < NCH; ++c) {
        CP_WAIT(1);
        __syncthreads();
        if (c + 2 < NCH) { issue_kv(c + 2); CP_COMMIT(); }

        const int p = c % NSTG;
        const uint32_t sKh = sb + AKV + p * KVST;
        const uint32_t sKl = sKh + KT;
        const uint32_t sVh = sKh + 2 * KT;
        const uint32_t sVl = sKh + 3 * KT;

        // ---- scores (base-2 domain; Q pre-scaled by log2e/8) ----
        float s[8][4];
#pragma unroll
        for (int i = 0; i < 8; i++)
#pragma unroll
            for (int j = 0; j < 4; j++) s[i][j] = 0.0f;

#pragma unroll
        for (int ks = 0; ks < 4; ks++) {
#pragma unroll
            for (int kp = 0; kp < 4; kp++) {
                uint32_t ro = (uint32_t)(kp * 16 + kb_row) * LDB + kb_kb + ks * 32;
                uint32_t rh[4], rl[4];
                ldm_x4(rh, sKh + ro);
                ldm_x4(rl, sKl + ro);
                uint32_t bh0[2] = { rh[0], rh[1] }, bh1[2] = { rh[2], rh[3] };
                uint32_t bl0[2] = { rl[0], rl[1] }, bl1[2] = { rl[2], rl[3] };
                mma16816(s[2 * kp],     qh[ks], bh0);
                mma16816(s[2 * kp],     qh[ks], bl0);
                mma16816(s[2 * kp],     ql[ks], bh0);
                mma16816(s[2 * kp + 1], qh[ks], bh1);
                mma16816(s[2 * kp + 1], qh[ks], bl1);
                mma16816(s[2 * kp + 1], ql[ks], bh1);
            }
        }

        // ---- shift-free softmax: P = exp2(s); accumulate L ----
#pragma unroll
        for (int i = 0; i < 8; i++) {
            s[i][0] = exp2f(s[i][0]);
            s[i][1] = exp2f(s[i][1]);
            s[i][2] = exp2f(s[i][2]);
            s[i][3] = exp2f(s[i][3]);
            L0a += s[i][0]; L0b += s[i][1];
            L1a += s[i][2]; L1b += s[i][3];
        }

        // ---- O += P . V ----
#pragma unroll
        for (int ks = 0; ks < 4; ks++) {
            uint32_t ph[4], pl[4];
            cvt_split2(s[2 * ks][0],     s[2 * ks][1],     ph[0], pl[0]);
            cvt_split2(s[2 * ks][2],     s[2 * ks][3],     ph[1], pl[1]);
            cvt_split2(s[2 * ks + 1][0], s[2 * ks + 1][1], ph[2], pl[2]);
            cvt_split2(s[2 * ks + 1][2], s[2 * ks + 1][3], ph[3], pl[3]);

            const uint32_t vro = (uint32_t)(ks * 16 + vb_row) * LDB + vb_nb;
#pragma unroll
            for (int ntp = 0; ntp < 4; ntp++) {
                uint32_t rh[4], rl[4];
                ldm_x4_t(rh, sVh + vro + ntp * 32);
                ldm_x4_t(rl, sVl + vro + ntp * 32);
                uint32_t vh0[2] = { rh[0], rh[1] }, vh1[2] = { rh[2], rh[3] };
                uint32_t vl0[2] = { rl[0], rl[1] }, vl1[2] = { rl[2], rl[3] };
                mma16816(O[2 * ntp],     ph, vh0);
                mma16816(O[2 * ntp],     ph, vl0);
                mma16816(O[2 * ntp],     pl, vh0);
                mma16816(O[2 * ntp + 1], ph, vh1);
                mma16816(O[2 * ntp + 1], ph, vl1);
                mma16816(O[2 * ntp + 1], pl, vh1);
            }
        }
    }

    // ---- finalize: reduce L, normalize, sin-mix, write split bf16 ----
    float L0 = L0a + L0b, L1 = L1a + L1b;
    L0 += __shfl_xor_sync(0xFFFFFFFF, L0, 1);
    L0 += __shfl_xor_sync(0xFFFFFFFF, L0, 2);
    L1 += __shfl_xor_sync(0xFFFFFFFF, L1, 1);
    L1 += __shfl_xor_sync(0xFFFFFFFF, L1, 2);
    const float inv0 = 1.0f / L0, inv1 = 1.0f / L1;
    const float wmix = 1.0f / (1.0f + __expf(-qw[h]));

    const int r0 = q0 + w * 16 + (lane >> 2);
    const int c0 = (lane & 3) * 2;
    __nv_bfloat16* oh0 = g_ah + base + (size_t)r0 * EMBED + c0;
    __nv_bfloat16* ol0 = g_al + base + (size_t)r0 * EMBED + c0;
    __nv_bfloat16* oh1 = g_ah + base + (size_t)(r0 + 8) * EMBED + c0;
    __nv_bfloat16* ol1 = g_al + base + (size_t)(r0 + 8) * EMBED + c0;
#pragma unroll
    for (int nt = 0; nt < 8; nt++) {
        float ca = O[nt][0] * inv0, cb = O[nt][1] * inv0;
        float cc = O[nt][2] * inv1, cd = O[nt][3] * inv1;
        float ma = wmix * sinf(ca) + (1.0f - wmix) * ca;
        float mb = wmix * sinf(cb) + (1.0f - wmix) * cb;
        float mc = wmix * sinf(cc) + (1.0f - wmix) * cc;
        float md = wmix * sinf(cd) + (1.0f - wmix) * cd;
        uint32_t hh, ll;
        cvt_split2(ma, mb, hh, ll);
        *(uint32_t*)(oh0 + nt * 8) = hh;
        *(uint32_t*)(ol0 + nt * 8) = ll;
        cvt_split2(mc, md, hh, ll);
        *(uint32_t*)(oh1 + nt * 8) = hh;
        *(uint32_t*)(ol1 + nt * 8) = ll;
    }
}

// ---------------------------------------------------------------------------
extern "C" void kernel_launch(void* const* d_in, const int* in_sizes, int n_in,
                              void* d_out, int out_size)
{
    const float* x  = (const float*)d_in[0];
    const float* Wq = (const float*)d_in[1];
    const float* Wk = (const float*)d_in[2];
    const float* Wv = (const float*)d_in[3];
    const float* Wo = (const float*)d_in[4];
    const float* qw = (const float*)d_in[5];
    float* out = (float*)d_out;

    const int M = in_sizes[0] / EMBED;   // B*S = 4096
    const int S = SEQ;
    const int B = M / S;

    static bool attr_done = false;
    if (!attr_done) {
        cudaFuncSetAttribute(qkv_tc_kernel, cudaFuncAttributeMaxDynamicSharedMemorySize, SMEM_GEMM);
        cudaFuncSetAttribute(out_tc_kernel, cudaFuncAttributeMaxDynamicSharedMemorySize, SMEM_GEMM);
        cudaFuncSetAttribute(attn_tc_kernel, cudaFuncAttributeMaxDynamicSharedMemorySize, SMEM_ATTN);
        attr_done = true;
    }

    __nv_bfloat16 *p_xh, *p_xl, *p_wh, *p_wl;
    cudaGetSymbolAddress((void**)&p_xh, g_xh);
    cudaGetSymbolAddress((void**)&p_xl, g_xl);
    cudaGetSymbolAddress((void**)&p_wh, g_wh);
    cudaGetSymbolAddress((void**)&p_wl, g_wl);

    // 0) Split x and weights into persistent hi/lo bf16
    {
        const int n4x = M * EMBED / 4;
        split_fp32_kernel<<<(n4x + 255) / 256, 256>>>(
            (const float4*)x, (uint2*)p_xh, (uint2*)p_xl, n4x);
        const int n4w = EMBED * EMBED / 4;
        dim3 gw((n4w + 255) / 256, 4);
        split_w_kernel<<<gw, 256>>>(
            (const float4*)Wq, (const float4*)Wk, (const float4*)Wv, (const float4*)Wo,
            (uint2*)p_wh, (uint2*)p_wl, n4w);
    }

    // 1) Q,K,V projections (Q pre-scaled by log2e/8)
    {
        dim3 grid(EMBED / TN, M / TM, 3);
        qkv_tc_kernel<<<grid, 512, SMEM_GEMM>>>();
    }
    // 2) Flash attention (shift-free softmax) + sin-mix epilogue
    {
        dim3 grid(S / 256, HEADS, B);
        attn_tc_kernel<<<grid, 512, SMEM_ATTN>>>(qw);
    }
    // 3) Output projection -> fp32 d_out
    {
        dim3 grid(EMBED / TN, M / TM, 1);
        out_tc_kernel<<<grid, 512, SMEM_GEMM>>>(out);
    }
}

// round 12
// speedup vs baseline: 1.3575x; 1.2937x over previous
#include <cuda_runtime.h>
#include <cuda_bf16.h>
#include <cuda_fp16.h>
#include <math.h>
#include <stdint.h>

#define EMBED 1024
#define HEADS 16
#define DK 64
#define SEQ 2048
#define MAXM 4096
#define NELEM (MAXM * EMBED)

// Persistent scratch (allocation-free rule: __device__ globals)
__device__ __nv_bfloat16 g_xh[NELEM], g_xl[NELEM];
__device__ __nv_bfloat16 g_wh[4 * EMBED * EMBED], g_wl[4 * EMBED * EMBED];
__device__ __half g_qh[NELEM], g_ql[NELEM];     // Q split fp16 (pre-scaled)
__device__ __half g_kf[NELEM];                  // K single fp16
__device__ __half g_vf[NELEM];                  // V single fp16
__device__ __nv_bfloat16 g_ah[NELEM], g_al[NELEM];  // attn out, split bf16

// ===========================================================================
// Common helpers
// ===========================================================================
__device__ __forceinline__ uint32_t smem_u32(const void* p) {
    uint32_t a;
    asm("{ .reg .u64 t; cvta.to.shared.u64 t, %1; cvt.u32.u64 %0, t; }"
        : "=r"(a) : "l"(p));
    return a;
}

__device__ __forceinline__ void ldm_x4(uint32_t* r, uint32_t addr) {
    asm volatile("ldmatrix.sync.aligned.m8n8.x4.shared.b16 {%0,%1,%2,%3}, [%4];"
                 : "=r"(r[0]), "=r"(r[1]), "=r"(r[2]), "=r"(r[3]) : "r"(addr));
}

__device__ __forceinline__ void ldm_x4_t(uint32_t* r, uint32_t addr) {
    asm volatile("ldmatrix.sync.aligned.m8n8.x4.trans.shared.b16 {%0,%1,%2,%3}, [%4];"
                 : "=r"(r[0]), "=r"(r[1]), "=r"(r[2]), "=r"(r[3]) : "r"(addr));
}

__device__ __forceinline__ void mma16816(float* d, const uint32_t* a, const uint32_t* b) {
    asm volatile(
        "mma.sync.aligned.m16n8k16.row.col.f32.bf16.bf16.f32 "
        "{%0,%1,%2,%3}, {%4,%5,%6,%7}, {%8,%9}, {%0,%1,%2,%3};"
        : "+f"(d[0]), "+f"(d[1]), "+f"(d[2]), "+f"(d[3])
        : "r"(a[0]), "r"(a[1]), "r"(a[2]), "r"(a[3]), "r"(b[0]), "r"(b[1]));
}

__device__ __forceinline__ void mma16816h(float* d, const uint32_t* a, const uint32_t* b) {
    asm volatile(
        "mma.sync.aligned.m16n8k16.row.col.f32.f16.f16.f32 "
        "{%0,%1,%2,%3}, {%4,%5,%6,%7}, {%8,%9}, {%0,%1,%2,%3};"
        : "+f"(d[0]), "+f"(d[1]), "+f"(d[2]), "+f"(d[3])
        : "r"(a[0]), "r"(a[1]), "r"(a[2]), "r"(a[3]), "r"(b[0]), "r"(b[1]));
}

__device__ __forceinline__ void cp_async16(uint32_t dst, const void* src) {
    asm volatile("cp.async.cg.shared.global [%0], [%1], 16;"
                 :: "r"(dst), "l"(src) : "memory");
}
#define CP_COMMIT() asm volatile("cp.async.commit_group;" ::: "memory")
#define CP_WAIT(N)  asm volatile("cp.async.wait_group %0;" :: "n"(N) : "memory")

__device__ __forceinline__ uint32_t packbf(__nv_bfloat16 a, __nv_bfloat16 b) {
    return (uint32_t)__bfloat16_as_ushort(a) | ((uint32_t)__bfloat16_as_ushort(b) << 16);
}

__device__ __forceinline__ uint32_t packh2(float a, float b) {
    __half2 h = __floats2half2_rn(a, b);
    return *reinterpret_cast<uint32_t*>(&h);
}

__device__ __forceinline__ void cvt_split4(float4 v, uint2& h, uint2& l) {
    __nv_bfloat16 h0 = __float2bfloat16(v.x);
    __nv_bfloat16 h1 = __float2bfloat16(v.y);
    __nv_bfloat16 h2 = __float2bfloat16(v.z);
    __nv_bfloat16 h3 = __float2bfloat16(v.w);
    __nv_bfloat16 l0 = __float2bfloat16(v.x - __bfloat162float(h0));
    __nv_bfloat16 l1 = __float2bfloat16(v.y - __bfloat162float(h1));
    __nv_bfloat16 l2 = __float2bfloat16(v.z - __bfloat162float(h2));
    __nv_bfloat16 l3 = __float2bfloat16(v.w - __bfloat162float(h3));
    h.x = packbf(h0, h1); h.y = packbf(h2, h3);
    l.x = packbf(l0, l1); l.y = packbf(l2, l3);
}

__device__ __forceinline__ void cvt_split2(float a, float b, uint32_t& h, uint32_t& l) {
    __nv_bfloat16 h0 = __float2bfloat16(a);
    __nv_bfloat16 h1 = __float2bfloat16(b);
    h = packbf(h0, h1);
    l = packbf(__float2bfloat16(a - __bfloat162float(h0)),
               __float2bfloat16(b - __bfloat162float(h1)));
}

__device__ __forceinline__ void cvt_split2h(float a, float b, uint32_t& h, uint32_t& l) {
    __half h0 = __float2half_rn(a);
    __half h1 = __float2half_rn(b);
    __half l0 = __float2half_rn(a - __half2float(h0));
    __half l1 = __float2half_rn(b - __half2float(h1));
    __half2 hp = __halves2half2(h0, h1), lp = __halves2half2(l0, l1);
    h = *reinterpret_cast<uint32_t*>(&hp);
    l = *reinterpret_cast<uint32_t*>(&lp);
}

// ===========================================================================
// Prep: split fp32 -> (hi, lo) bf16
// ===========================================================================
__global__ __launch_bounds__(256) void split_fp32_kernel(
    const float4* __restrict__ src, uint2* __restrict__ hi, uint2* __restrict__ lo, int n4)
{
    int i = blockIdx.x * blockDim.x + threadIdx.x;
    if (i < n4) {
        uint2 h, l;
        cvt_split4(src[i], h, l);
        hi[i] = h;
        lo[i] = l;
    }
}

__global__ __launch_bounds__(256) void split_w_kernel(
    const float4* __restrict__ w0, const float4* __restrict__ w1,
    const float4* __restrict__ w2, const float4* __restrict__ w3,
    uint2* __restrict__ hi, uint2* __restrict__ lo, int n4)
{
    const int z = blockIdx.y;
    const float4* src = (z == 0) ? w0 : (z == 1) ? w1 : (z == 2) ? w2 : w3;
    int i = blockIdx.x * blockDim.x + threadIdx.x;
    if (i < n4) {
        uint2 h, l;
        cvt_split4(src[i], h, l);
        hi[(size_t)z * n4 + i] = h;
        lo[(size_t)z * n4 + i] = l;
    }
}

// ===========================================================================
// GEMM on pre-split bf16 (mainloop unchanged from R9); epilogue mode:
//  0 = fp32, 2 = split fp16 (Q), 3 = single fp16 (K/V)
// ===========================================================================
#define TM 128
#define TN 128
#define KCH 64
#define LDB 144
#define GT (128 * LDB)
#define GSTAGE (4 * GT)
#define NSTG 3
#define SMEM_GEMM (NSTG * GSTAGE)

__device__ __forceinline__ void gemm_bf16_body(
    const __nv_bfloat16* __restrict__ Ah, const __nv_bfloat16* __restrict__ Al,
    const __nv_bfloat16* __restrict__ Bh, const __nv_bfloat16* __restrict__ Bl,
    float* __restrict__ Cf,
    __half* __restrict__ Ch, __half* __restrict__ Cl,
    float scale, int mode)
{
    extern __shared__ char smem[];
    const uint32_t sbase = smem_u32(smem);
    const int tid  = threadIdx.x;
    const int lane = tid & 31;
    const int wid  = tid >> 5;
    const int wm   = wid & 3;
    const int wn   = wid >> 2;
    const int m0 = blockIdx.y * TM;
    const int n0 = blockIdx.x * TN;

    float acc[2][4][4];
#pragma unroll
    for (int i = 0; i < 2; i++)
#pragma unroll
        for (int j = 0; j < 4; j++)
#pragma unroll
            for (int r = 0; r < 4; r++) acc[i][j][r] = 0.0f;

    int lrow[2], lu4[2];
#pragma unroll
    for (int i = 0; i < 2; i++) {
        int idx = tid + i * 512;
        lrow[i] = idx >> 3;
        lu4[i]  = idx & 7;
    }

    const __nv_bfloat16* Abh = Ah + (size_t)m0 * EMBED;
    const __nv_bfloat16* Abl = Al + (size_t)m0 * EMBED;
    const __nv_bfloat16* Bbh = Bh + (size_t)n0 * EMBED;
    const __nv_bfloat16* Bbl = Bl + (size_t)n0 * EMBED;

    const int NCHUNK = EMBED / KCH;

    auto issue = [&](int c) {
        const uint32_t stu = sbase + (c % NSTG) * GSTAGE;
        const int koff = c * KCH;
#pragma unroll
        for (int i = 0; i < 2; i++) {
            size_t off = (size_t)lrow[i] * EMBED + koff + lu4[i] * 8;
            uint32_t bo = lrow[i] * LDB + lu4[i] * 16;
            cp_async16(stu + 0 * GT + bo, Abh + off);
            cp_async16(stu + 1 * GT + bo, Abl + off);
            cp_async16(stu + 2 * GT + bo, Bbh + off);
            cp_async16(stu + 3 * GT + bo, Bbl + off);
        }
    };

    issue(0); CP_COMMIT();
    issue(1); CP_COMMIT();

    const int a_row = wm * 32 + (lane & 15);
    const int a_kb  = (lane >> 4) * 16;
    const int b_row = wn * 32 + ((lane >> 4) & 1) * 8 + (lane & 7);
    const int b_kb  = ((lane >> 3) & 1) * 16;

    for (int c = 0; c < NCHUNK; ++c) {
        CP_WAIT(1);
        __syncthreads();
        if (c + 2 < NCHUNK) { issue(c + 2); CP_COMMIT(); }

        const int p = c % NSTG;
        const uint32_t sAh = sbase + p * GSTAGE;
        const uint32_t sAl = sAh + GT;
        const uint32_t sBh = sAh + 2 * GT;
        const uint32_t sBl = sAh + 3 * GT;

#pragma unroll
        for (int ks = 0; ks < 4; ++ks) {
            uint32_t ah[2][4], al[2][4];
            uint32_t bh[4][2], bl[4][2];

            const uint32_t akoff = ks * 32 + a_kb;
#pragma unroll
            for (int mi = 0; mi < 2; mi++) {
                uint32_t ro = (uint32_t)(a_row + mi * 16) * LDB + akoff;
                ldm_x4(ah[mi], sAh + ro);
                ldm_x4(al[mi], sAl + ro);
            }
            const uint32_t bkoff = ks * 32 + b_kb;
#pragma unroll
            for (int np = 0; np < 2; np++) {
                uint32_t ro = (uint32_t)(b_row + np * 16) * LDB + bkoff;
                uint32_t r[4];
                ldm_x4(r, sBh + ro);
                bh[np * 2][0] = r[0]; bh[np * 2][1] = r[1];
                bh[np * 2 + 1][0] = r[2]; bh[np * 2 + 1][1] = r[3];
                ldm_x4(r, sBl + ro);
                bl[np * 2][0] = r[0]; bl[np * 2][1] = r[1];
                bl[np * 2 + 1][0] = r[2]; bl[np * 2 + 1][1] = r[3];
            }

#pragma unroll
            for (int mi = 0; mi < 2; mi++)
#pragma unroll
                for (int ni = 0; ni < 4; ni++) {
                    mma16816(acc[mi][ni], ah[mi], bh[ni]);
                    mma16816(acc[mi][ni], ah[mi], bl[ni]);
                    mma16816(acc[mi][ni], al[mi], bh[ni]);
                }
        }
    }

    const int er = lane >> 2;
    const int ec = (lane & 3) * 2;
#pragma unroll
    for (int mi = 0; mi < 2; mi++) {
#pragma unroll
        for (int ni = 0; ni < 4; ni++) {
            int row = m0 + wm * 32 + mi * 16 + er;
            int col = n0 + wn * 32 + ni * 8 + ec;
            float a0 = acc[mi][ni][0] * scale, a1 = acc[mi][ni][1] * scale;
            float a2 = acc[mi][ni][2] * scale, a3 = acc[mi][ni][3] * scale;
            if (mode == 0) {
                *(float2*)(Cf + (size_t)row * EMBED + col) = make_float2(a0, a1);
                *(float2*)(Cf + (size_t)(row + 8) * EMBED + col) = make_float2(a2, a3);
            } else if (mode == 2) {
                uint32_t h, l;
                cvt_split2h(a0, a1, h, l);
                *(uint32_t*)(Ch + (size_t)row * EMBED + col) = h;
                *(uint32_t*)(Cl + (size_t)row * EMBED + col) = l;
                cvt_split2h(a2, a3, h, l);
                *(uint32_t*)(Ch + (size_t)(row + 8) * EMBED + col) = h;
                *(uint32_t*)(Cl + (size_t)(row + 8) * EMBED + col) = l;
            } else {
                *(uint32_t*)(Ch + (size_t)row * EMBED + col) = packh2(a0, a1);
                *(uint32_t*)(Ch + (size_t)(row + 8) * EMBED + col) = packh2(a2, a3);
            }
        }
    }
}

__global__ __launch_bounds__(512, 1) void qkv_tc_kernel()
{
    const int z = blockIdx.z;
    const __nv_bfloat16* Bh = g_wh + (size_t)z * EMBED * EMBED;
    const __nv_bfloat16* Bl = g_wl + (size_t)z * EMBED * EMBED;
    if (z == 0)       // Q: split fp16, scale folds 1/sqrt(DK) * log2(e)
        gemm_bf16_body(g_xh, g_xl, Bh, Bl, nullptr, g_qh, g_ql,
                       0.125f * 1.4426950408889634f, 2);
    else if (z == 1)  // K: single fp16
        gemm_bf16_body(g_xh, g_xl, Bh, Bl, nullptr, g_kf, nullptr, 1.0f, 3);
    else              // V: single fp16
        gemm_bf16_body(g_xh, g_xl, Bh, Bl, nullptr, g_vf, nullptr, 1.0f, 3);
}

__global__ __launch_bounds__(512, 1) void out_tc_kernel(float* __restrict__ out)
{
    gemm_bf16_body(g_ah, g_al,
                   g_wh + (size_t)3 * EMBED * EMBED, g_wl + (size_t)3 * EMBED * EMBED,
                   out, nullptr, nullptr, 1.0f, 0);
}

// ===========================================================================
// Tensor-core flash attention, fp16 datapath:
//   scores = (Qh + Ql)(fp16 split) . K(fp16)   -> 2 MMAs per product
//   O     += P(fp16) . V(fp16)                 -> 1 MMA per product
// Shift-free base-2 softmax. 512 threads, 256 q-rows, 64-key chunks.
// ===========================================================================
#define KT (64 * LDB)                  // 9216
#define QT (256 * LDB)                 // 36864
#define AQH 0
#define AQL QT
#define AKV (2 * QT)
#define KVST (2 * KT)                  // Kf, Vf per stage = 18432
#define SMEM_ATTN (2 * QT + NSTG * KVST)  // 129024

__global__ __launch_bounds__(512, 1) void attn_tc_kernel(
    const float* __restrict__ qw)
{
    extern __shared__ char smem[];
    const uint32_t sb = smem_u32(smem);
    const int tid  = threadIdx.x;
    const int lane = tid & 31;
    const int w    = tid >> 5;
    const int h = blockIdx.y;
    const int b = blockIdx.z;
    const int q0 = blockIdx.x * 256;

    const size_t base = (size_t)b * SEQ * EMBED + (size_t)h * DK;

    const int krow = tid >> 3;
    const int ku4  = tid & 7;

    auto issue_kv = [&](int c) {
        const uint32_t stu = sb + AKV + (c % NSTG) * KVST;
        size_t off = base + (size_t)(c * 64 + krow) * EMBED + ku4 * 8;
        uint32_t bo = krow * LDB + ku4 * 16;
        cp_async16(stu + 0 * KT + bo, g_kf + off);
        cp_async16(stu + 1 * KT + bo, g_vf + off);
    };

    issue_kv(0); CP_COMMIT();
    issue_kv(1); CP_COMMIT();

    // ---- copy pre-split fp16 Q tile into SMEM ----
    {
        const __half* Qh = g_qh + base + (size_t)q0 * EMBED;
        const __half* Ql = g_ql + base + (size_t)q0 * EMBED;
#pragma unroll
        for (int i = 0; i < 4; i++) {
            int idx = i * 512 + tid;
            int row = idx >> 3, u4 = idx & 7;
            size_t off = (size_t)row * EMBED + u4 * 8;
            uint32_t bo = row * LDB + u4 * 16;
            *(uint4*)(smem + AQH + bo) = *(const uint4*)(Qh + off);
            *(uint4*)(smem + AQL + bo) = *(const uint4*)(Ql + off);
        }
    }
    __syncthreads();

    // ---- Q fragments (fp16), register resident ----
    uint32_t qh[4][4], ql[4][4];
    {
        const uint32_t aoff = (uint32_t)(w * 16 + (lane & 15)) * LDB + (lane >> 4) * 16;
#pragma unroll
        for (int ks = 0; ks < 4; ks++) {
            ldm_x4(qh[ks], sb + AQH + aoff + ks * 32);
            ldm_x4(ql[ks], sb + AQL + aoff + ks * 32);
        }
    }

    float O[8][4];
#pragma unroll
    for (int i = 0; i < 8; i++)
#pragma unroll
        for (int j = 0; j < 4; j++) O[i][j] = 0.0f;
    float L0a = 0.0f, L0b = 0.0f, L1a = 0.0f, L1b = 0.0f;

    const uint32_t kb_row = ((lane >> 4) & 1) * 8 + (lane & 7);
    const uint32_t kb_kb  = ((lane >> 3) & 1) * 16;
    const uint32_t vb_row = ((lane >> 3) & 1) * 8 + (lane & 7);
    const uint32_t vb_nb  = (lane >> 4) * 16;

    const int NCH = SEQ / 64;   // 32
    for (int c = 0; c < NCH; ++c) {
        CP_WAIT(1);
        __syncthreads();
        if (c + 2 < NCH) { issue_kv(c + 2); CP_COMMIT(); }

        const int p = c % NSTG;
        const uint32_t sKf = sb + AKV + p * KVST;
        const uint32_t sVf = sKf + KT;

        // ---- scores: 2 fp16 MMAs per 16-key x 16-k product ----
        float s[8][4];
#pragma unroll
        for (int i = 0; i < 8; i++)
#pragma unroll
            for (int j = 0; j < 4; j++) s[i][j] = 0.0f;

#pragma unroll
        for (int ks = 0; ks < 4; ks++) {
#pragma unroll
            for (int kp = 0; kp < 4; kp++) {
                uint32_t ro = (uint32_t)(kp * 16 + kb_row) * LDB + kb_kb + ks * 32;
                uint32_t r[4];
                ldm_x4(r, sKf + ro);
                uint32_t b0[2] = { r[0], r[1] }, b1[2] = { r[2], r[3] };
                mma16816h(s[2 * kp],     qh[ks], b0);
                mma16816h(s[2 * kp],     ql[ks], b0);
                mma16816h(s[2 * kp + 1], qh[ks], b1);
                mma16816h(s[2 * kp + 1], ql[ks], b1);
            }
        }

        // ---- shift-free softmax: P = exp2(s) ----
#pragma unroll
        for (int i = 0; i < 8; i++) {
            s[i][0] = exp2f(s[i][0]);
            s[i][1] = exp2f(s[i][1]);
            s[i][2] = exp2f(s[i][2]);
            s[i][3] = exp2f(s[i][3]);
            L0a += s[i][0]; L0b += s[i][1];
            L1a += s[i][2]; L1b += s[i][3];
        }

        // ---- O += P(fp16) . V(fp16): 1 MMA per product ----
#pragma unroll
        for (int ks = 0; ks < 4; ks++) {
            uint32_t ph[4];
            ph[0] = packh2(s[2 * ks][0],     s[2 * ks][1]);
            ph[1] = packh2(s[2 * ks][2],     s[2 * ks][3]);
            ph[2] = packh2(s[2 * ks + 1][0], s[2 * ks + 1][1]);
            ph[3] = packh2(s[2 * ks + 1][2], s[2 * ks + 1][3]);

            const uint32_t vro = (uint32_t)(ks * 16 + vb_row) * LDB + vb_nb;
#pragma unroll
            for (int ntp = 0; ntp < 4; ntp++) {
                uint32_t r[4];
                ldm_x4_t(r, sVf + vro + ntp * 32);
                uint32_t v0[2] = { r[0], r[1] }, v1[2] = { r[2], r[3] };
                mma16816h(O[2 * ntp],     ph, v0);
                mma16816h(O[2 * ntp + 1], ph, v1);
            }
        }
    }

    // ---- finalize: reduce L, normalize, sin-mix, write split bf16 ----
    float L0 = L0a + L0b, L1 = L1a + L1b;
    L0 += __shfl_xor_sync(0xFFFFFFFF, L0, 1);
    L0 += __shfl_xor_sync(0xFFFFFFFF, L0, 2);
    L1 += __shfl_xor_sync(0xFFFFFFFF, L1, 1);
    L1 += __shfl_xor_sync(0xFFFFFFFF, L1, 2);
    const float inv0 = 1.0f / L0, inv1 = 1.0f / L1;
    const float wmix = 1.0f / (1.0f + __expf(-qw[h]));

    const int r0 = q0 + w * 16 + (lane >> 2);
    const int c0 = (lane & 3) * 2;
    __nv_bfloat16* oh0 = g_ah + base + (size_t)r0 * EMBED + c0;
    __nv_bfloat16* ol0 = g_al + base + (size_t)r0 * EMBED + c0;
    __nv_bfloat16* oh1 = g_ah + base + (size_t)(r0 + 8) * EMBED + c0;
    __nv_bfloat16* ol1 = g_al + base + (size_t)(r0 + 8) * EMBED + c0;
#pragma unroll
    for (int nt = 0; nt < 8; nt++) {
        float ca = O[nt][0] * inv0, cb = O[nt][1] * inv0;
        float cc = O[nt][2] * inv1, cd = O[nt][3] * inv1;
        float ma = wmix * sinf(ca) + (1.0f - wmix) * ca;
        float mb = wmix * sinf(cb) + (1.0f - wmix) * cb;
        float mc = wmix * sinf(cc) + (1.0f - wmix) * cc;
        float md = wmix * sinf(cd) + (1.0f - wmix) * cd;
        uint32_t hh, ll;
        cvt_split2(ma, mb, hh, ll);
        *(uint32_t*)(oh0 + nt * 8) = hh;
        *(uint32_t*)(ol0 + nt * 8) = ll;
        cvt_split2(mc, md, hh, ll);
        *(uint32_t*)(oh1 + nt * 8) = hh;
        *(uint32_t*)(ol1 + nt * 8) = ll;
    }
}

// ---------------------------------------------------------------------------
extern "C" void kernel_launch(void* const* d_in, const int* in_sizes, int n_in,
                              void* d_out, int out_size)
{
    const float* x  = (const float*)d_in[0];
    const float* Wq = (const float*)d_in[1];
    const float* Wk = (const float*)d_in[2];
    const float* Wv = (const float*)d_in[3];
    const float* Wo = (const float*)d_in[4];
    const float* qw = (const float*)d_in[5];
    float* out = (float*)d_out;

    const int M = in_sizes[0] / EMBED;   // B*S = 4096
    const int S = SEQ;
    const int B = M / S;

    static bool attr_done = false;
    if (!attr_done) {
        cudaFuncSetAttribute(qkv_tc_kernel, cudaFuncAttributeMaxDynamicSharedMemorySize, SMEM_GEMM);
        cudaFuncSetAttribute(out_tc_kernel, cudaFuncAttributeMaxDynamicSharedMemorySize, SMEM_GEMM);
        cudaFuncSetAttribute(attn_tc_kernel, cudaFuncAttributeMaxDynamicSharedMemorySize, SMEM_ATTN);
        attr_done = true;
    }

    __nv_bfloat16 *p_xh, *p_xl, *p_wh, *p_wl;
    cudaGetSymbolAddress((void**)&p_xh, g_xh);
    cudaGetSymbolAddress((void**)&p_xl, g_xl);
    cudaGetSymbolAddress((void**)&p_wh, g_wh);
    cudaGetSymbolAddress((void**)&p_wl, g_wl);

    // 0) Split x and weights into persistent hi/lo bf16
    {
        const int n4x = M * EMBED / 4;
        split_fp32_kernel<<<(n4x + 255) / 256, 256>>>(
            (const float4*)x, (uint2*)p_xh, (uint2*)p_xl, n4x);
        const int n4w = EMBED * EMBED / 4;
        dim3 gw((n4w + 255) / 256, 4);
        split_w_kernel<<<gw, 256>>>(
            (const float4*)Wq, (const float4*)Wk, (const float4*)Wv, (const float4*)Wo,
            (uint2*)p_wh, (uint2*)p_wl, n4w);
    }

    // 1) Q,K,V projections (Q split fp16 pre-scaled; K,V single fp16)
    {
        dim3 grid(EMBED / TN, M / TM, 3);
        qkv_tc_kernel<<<grid, 512, SMEM_GEMM>>>();
    }
    // 2) Flash attention (fp16 datapath, shift-free softmax) + sin-mix
    {
        dim3 grid(S / 256, HEADS, B);
        attn_tc_kernel<<<grid, 512, SMEM_ATTN>>>(qw);
    }
    // 3) Output projection -> fp32 d_out
    {
        dim3 grid(EMBED / TN, M / TM, 1);
        out_tc_kernel<<<grid, 512, SMEM_GEMM>>>(out);
    }
}

// round 13
// speedup vs baseline: 1.6889x; 1.2441x over previous
#include <cuda_runtime.h>
#include <cuda_bf16.h>
#include <cuda_fp16.h>
#include <math.h>
#include <stdint.h>

#define EMBED 1024
#define HEADS 16
#define DK 64
#define SEQ 2048
#define MAXM 4096
#define NELEM (MAXM * EMBED)

// Persistent scratch (allocation-free rule: __device__ globals)
__device__ __half g_xh[NELEM], g_xl[NELEM];       // x split fp16
__device__ __half g_wf[4 * EMBED * EMBED];        // weights single fp16
__device__ __half g_qh[NELEM], g_ql[NELEM];       // Q split fp16 (pre-scaled)
__device__ __half g_kf[NELEM];                    // K single fp16
__device__ __half g_vf[NELEM];                    // V single fp16
__device__ __half g_ah[NELEM], g_al[NELEM];       // attn out split fp16

// ===========================================================================
// Common helpers
// ===========================================================================
__device__ __forceinline__ uint32_t smem_u32(const void* p) {
    uint32_t a;
    asm("{ .reg .u64 t; cvta.to.shared.u64 t, %1; cvt.u32.u64 %0, t; }"
        : "=r"(a) : "l"(p));
    return a;
}

__device__ __forceinline__ void ldm_x4(uint32_t* r, uint32_t addr) {
    asm volatile("ldmatrix.sync.aligned.m8n8.x4.shared.b16 {%0,%1,%2,%3}, [%4];"
                 : "=r"(r[0]), "=r"(r[1]), "=r"(r[2]), "=r"(r[3]) : "r"(addr));
}

__device__ __forceinline__ void ldm_x4_t(uint32_t* r, uint32_t addr) {
    asm volatile("ldmatrix.sync.aligned.m8n8.x4.trans.shared.b16 {%0,%1,%2,%3}, [%4];"
                 : "=r"(r[0]), "=r"(r[1]), "=r"(r[2]), "=r"(r[3]) : "r"(addr));
}

__device__ __forceinline__ void mma16816h(float* d, const uint32_t* a, const uint32_t* b) {
    asm volatile(
        "mma.sync.aligned.m16n8k16.row.col.f32.f16.f16.f32 "
        "{%0,%1,%2,%3}, {%4,%5,%6,%7}, {%8,%9}, {%0,%1,%2,%3};"
        : "+f"(d[0]), "+f"(d[1]), "+f"(d[2]), "+f"(d[3])
        : "r"(a[0]), "r"(a[1]), "r"(a[2]), "r"(a[3]), "r"(b[0]), "r"(b[1]));
}

__device__ __forceinline__ void cp_async16(uint32_t dst, const void* src) {
    asm volatile("cp.async.cg.shared.global [%0], [%1], 16;"
                 :: "r"(dst), "l"(src) : "memory");
}
#define CP_COMMIT() asm volatile("cp.async.commit_group;" ::: "memory")
#define CP_WAIT(N)  asm volatile("cp.async.wait_group %0;" :: "n"(N) : "memory")

__device__ __forceinline__ uint32_t packh2(float a, float b) {
    __half2 h = __floats2half2_rn(a, b);
    return *reinterpret_cast<uint32_t*>(&h);
}

__device__ __forceinline__ void cvt_split2h(float a, float b, uint32_t& h, uint32_t& l) {
    __half h0 = __float2half_rn(a);
    __half h1 = __float2half_rn(b);
    __half l0 = __float2half_rn(a - __half2float(h0));
    __half l1 = __float2half_rn(b - __half2float(h1));
    __half2 hp = __halves2half2(h0, h1), lp = __halves2half2(l0, l1);
    h = *reinterpret_cast<uint32_t*>(&hp);
    l = *reinterpret_cast<uint32_t*>(&lp);
}

__device__ __forceinline__ void cvt_split4h(float4 v, uint2& h, uint2& l) {
    cvt_split2h(v.x, v.y, h.x, l.x);
    cvt_split2h(v.z, v.w, h.y, l.y);
}

// ===========================================================================
// Prep kernels
// ===========================================================================
__global__ __launch_bounds__(256) void split_x_kernel(
    const float4* __restrict__ src, uint2* __restrict__ hi, uint2* __restrict__ lo, int n4)
{
    int i = blockIdx.x * blockDim.x + threadIdx.x;
    if (i < n4) {
        uint2 h, l;
        cvt_split4h(src[i], h, l);
        hi[i] = h;
        lo[i] = l;
    }
}

__global__ __launch_bounds__(256) void cvt_w_kernel(
    const float4* __restrict__ w0, const float4* __restrict__ w1,
    const float4* __restrict__ w2, const float4* __restrict__ w3,
    uint2* __restrict__ dst, int n4)
{
    const int z = blockIdx.y;
    const float4* src = (z == 0) ? w0 : (z == 1) ? w1 : (z == 2) ? w2 : w3;
    int i = blockIdx.x * blockDim.x + threadIdx.x;
    if (i < n4) {
        float4 v = src[i];
        uint2 d;
        d.x = packh2(v.x, v.y);
        d.y = packh2(v.z, v.w);
        dst[(size_t)z * n4 + i] = d;
    }
}

// ===========================================================================
// GEMM: C[m,n] = sum_k A[m,k]*B[n,k]  (NT)
// A = split fp16 (hi+lo), B = single fp16 -> 2 MMAs per 16x16 product.
// CTA 128x128, 512 threads (16 warps 4x4, warp tile 32x32), K-chunk 64,
// 3-stage cp.async pipeline. Epilogue mode: 0=fp32, 2=split fp16, 3=single fp16.
// ===========================================================================
#define TM 128
#define TN 128
#define KCH 64
#define LDB 144
#define GT (128 * LDB)             // 18432 per 128x64 fp16 tile
#define GSTAGE (3 * GT)            // Ah Al B = 55296
#define NSTG 3
#define SMEM_GEMM (NSTG * GSTAGE)  // 165888

__device__ __forceinline__ void gemm_f16_body(
    const __half* __restrict__ Ah, const __half* __restrict__ Al,
    const __half* __restrict__ Bf,
    float* __restrict__ Cf,
    __half* __restrict__ Ch, __half* __restrict__ Cl,
    float scale, int mode)
{
    extern __shared__ char smem[];
    const uint32_t sbase = smem_u32(smem);
    const int tid  = threadIdx.x;
    const int lane = tid & 31;
    const int wid  = tid >> 5;
    const int wm   = wid & 3;
    const int wn   = wid >> 2;
    const int m0 = blockIdx.y * TM;
    const int n0 = blockIdx.x * TN;

    float acc[2][4][4];
#pragma unroll
    for (int i = 0; i < 2; i++)
#pragma unroll
        for (int j = 0; j < 4; j++)
#pragma unroll
            for (int r = 0; r < 4; r++) acc[i][j][r] = 0.0f;

    int lrow[2], lu4[2];
#pragma unroll
    for (int i = 0; i < 2; i++) {
        int idx = tid + i * 512;
        lrow[i] = idx >> 3;
        lu4[i]  = idx & 7;
    }

    const __half* Abh = Ah + (size_t)m0 * EMBED;
    const __half* Abl = Al + (size_t)m0 * EMBED;
    const __half* Bb  = Bf + (size_t)n0 * EMBED;

    const int NCHUNK = EMBED / KCH;

    auto issue = [&](int c) {
        const uint32_t stu = sbase + (c % NSTG) * GSTAGE;
        const int koff = c * KCH;
#pragma unroll
        for (int i = 0; i < 2; i++) {
            size_t off = (size_t)lrow[i] * EMBED + koff + lu4[i] * 8;
            uint32_t bo = lrow[i] * LDB + lu4[i] * 16;
            cp_async16(stu + 0 * GT + bo, Abh + off);
            cp_async16(stu + 1 * GT + bo, Abl + off);
            cp_async16(stu + 2 * GT + bo, Bb + off);
        }
    };

    issue(0); CP_COMMIT();
    issue(1); CP_COMMIT();

    const int a_row = wm * 32 + (lane & 15);
    const int a_kb  = (lane >> 4) * 16;
    const int b_row = wn * 32 + ((lane >> 4) & 1) * 8 + (lane & 7);
    const int b_kb  = ((lane >> 3) & 1) * 16;

    for (int c = 0; c < NCHUNK; ++c) {
        CP_WAIT(1);
        __syncthreads();
        if (c + 2 < NCHUNK) { issue(c + 2); CP_COMMIT(); }

        const int p = c % NSTG;
        const uint32_t sAh = sbase + p * GSTAGE;
        const uint32_t sAl = sAh + GT;
        const uint32_t sB  = sAh + 2 * GT;

#pragma unroll
        for (int ks = 0; ks < 4; ++ks) {
            uint32_t ah[2][4], al[2][4];
            uint32_t bh[4][2];

            const uint32_t akoff = ks * 32 + a_kb;
#pragma unroll
            for (int mi = 0; mi < 2; mi++) {
                uint32_t ro = (uint32_t)(a_row + mi * 16) * LDB + akoff;
                ldm_x4(ah[mi], sAh + ro);
                ldm_x4(al[mi], sAl + ro);
            }
            const uint32_t bkoff = ks * 32 + b_kb;
#pragma unroll
            for (int np = 0; np < 2; np++) {
                uint32_t ro = (uint32_t)(b_row + np * 16) * LDB + bkoff;
                uint32_t r[4];
                ldm_x4(r, sB + ro);
                bh[np * 2][0] = r[0]; bh[np * 2][1] = r[1];
                bh[np * 2 + 1][0] = r[2]; bh[np * 2 + 1][1] = r[3];
            }

#pragma unroll
            for (int mi = 0; mi < 2; mi++)
#pragma unroll
                for (int ni = 0; ni < 4; ni++) {
                    mma16816h(acc[mi][ni], ah[mi], bh[ni]);
                    mma16816h(acc[mi][ni], al[mi], bh[ni]);
                }
        }
    }

    const int er = lane >> 2;
    const int ec = (lane & 3) * 2;
#pragma unroll
    for (int mi = 0; mi < 2; mi++) {
#pragma unroll
        for (int ni = 0; ni < 4; ni++) {
            int row = m0 + wm * 32 + mi * 16 + er;
            int col = n0 + wn * 32 + ni * 8 + ec;
            float a0 = acc[mi][ni][0] * scale, a1 = acc[mi][ni][1] * scale;
            float a2 = acc[mi][ni][2] * scale, a3 = acc[mi][ni][3] * scale;
            if (mode == 0) {
                *(float2*)(Cf + (size_t)row * EMBED + col) = make_float2(a0, a1);
                *(float2*)(Cf + (size_t)(row + 8) * EMBED + col) = make_float2(a2, a3);
            } else if (mode == 2) {
                uint32_t h, l;
                cvt_split2h(a0, a1, h, l);
                *(uint32_t*)(Ch + (size_t)row * EMBED + col) = h;
                *(uint32_t*)(Cl + (size_t)row * EMBED + col) = l;
                cvt_split2h(a2, a3, h, l);
                *(uint32_t*)(Ch + (size_t)(row + 8) * EMBED + col) = h;
                *(uint32_t*)(Cl + (size_t)(row + 8) * EMBED + col) = l;
            } else {
                *(uint32_t*)(Ch + (size_t)row * EMBED + col) = packh2(a0, a1);
                *(uint32_t*)(Ch + (size_t)(row + 8) * EMBED + col) = packh2(a2, a3);
            }
        }
    }
}

__global__ __launch_bounds__(512, 1) void qkv_tc_kernel()
{
    const int z = blockIdx.z;
    const __half* Bf = g_wf + (size_t)z * EMBED * EMBED;
    if (z == 0)       // Q: split fp16, scale folds 1/sqrt(DK) * log2(e)
        gemm_f16_body(g_xh, g_xl, Bf, nullptr, g_qh, g_ql,
                      0.125f * 1.4426950408889634f, 2);
    else if (z == 1)  // K: single fp16
        gemm_f16_body(g_xh, g_xl, Bf, nullptr, g_kf, nullptr, 1.0f, 3);
    else              // V: single fp16
        gemm_f16_body(g_xh, g_xl, Bf, nullptr, g_vf, nullptr, 1.0f, 3);
}

__global__ __launch_bounds__(512, 1) void out_tc_kernel(float* __restrict__ out)
{
    gemm_f16_body(g_ah, g_al, g_wf + (size_t)3 * EMBED * EMBED,
                  out, nullptr, nullptr, 1.0f, 0);
}

// ===========================================================================
// Tensor-core flash attention, fp16 datapath (unchanged from R12):
//   scores = (Qh + Ql) . K  -> 2 MMAs;  O += P . V -> 1 MMA
// Shift-free base-2 softmax. 512 threads, 256 q-rows, 64-key chunks.
// Output written split fp16 for the out-projection.
// ===========================================================================
#define KT (64 * LDB)
#define QT (256 * LDB)
#define AQH 0
#define AQL QT
#define AKV (2 * QT)
#define KVST (2 * KT)
#define SMEM_ATTN (2 * QT + NSTG * KVST)

__global__ __launch_bounds__(512, 1) void attn_tc_kernel(
    const float* __restrict__ qw)
{
    extern __shared__ char smem[];
    const uint32_t sb = smem_u32(smem);
    const int tid  = threadIdx.x;
    const int lane = tid & 31;
    const int w    = tid >> 5;
    const int h = blockIdx.y;
    const int b = blockIdx.z;
    const int q0 = blockIdx.x * 256;

    const size_t base = (size_t)b * SEQ * EMBED + (size_t)h * DK;

    const int krow = tid >> 3;
    const int ku4  = tid & 7;

    auto issue_kv = [&](int c) {
        const uint32_t stu = sb + AKV + (c % NSTG) * KVST;
        size_t off = base + (size_t)(c * 64 + krow) * EMBED + ku4 * 8;
        uint32_t bo = krow * LDB + ku4 * 16;
        cp_async16(stu + 0 * KT + bo, g_kf + off);
        cp_async16(stu + 1 * KT + bo, g_vf + off);
    };

    issue_kv(0); CP_COMMIT();
    issue_kv(1); CP_COMMIT();

    {
        const __half* Qh = g_qh + base + (size_t)q0 * EMBED;
        const __half* Ql = g_ql + base + (size_t)q0 * EMBED;
#pragma unroll
        for (int i = 0; i < 4; i++) {
            int idx = i * 512 + tid;
            int row = idx >> 3, u4 = idx & 7;
            size_t off = (size_t)row * EMBED + u4 * 8;
            uint32_t bo = row * LDB + u4 * 16;
            *(uint4*)(smem + AQH + bo) = *(const uint4*)(Qh + off);
            *(uint4*)(smem + AQL + bo) = *(const uint4*)(Ql + off);
        }
    }
    __syncthreads();

    uint32_t qh[4][4], ql[4][4];
    {
        const uint32_t aoff = (uint32_t)(w * 16 + (lane & 15)) * LDB + (lane >> 4) * 16;
#pragma unroll
        for (int ks = 0; ks < 4; ks++) {
            ldm_x4(qh[ks], sb + AQH + aoff + ks * 32);
            ldm_x4(ql[ks], sb + AQL + aoff + ks * 32);
        }
    }

    float O[8][4];
#pragma unroll
    for (int i = 0; i < 8; i++)
#pragma unroll
        for (int j = 0; j < 4; j++) O[i][j] = 0.0f;
    float L0a = 0.0f, L0b = 0.0f, L1a = 0.0f, L1b = 0.0f;

    const uint32_t kb_row = ((lane >> 4) & 1) * 8 + (lane & 7);
    const uint32_t kb_kb  = ((lane >> 3) & 1) * 16;
    const uint32_t vb_row = ((lane >> 3) & 1) * 8 + (lane & 7);
    const uint32_t vb_nb  = (lane >> 4) * 16;

    const int NCH = SEQ / 64;   // 32
    for (int c = 0; c < NCH; ++c) {
        CP_WAIT(1);
        __syncthreads();
        if (c + 2 < NCH) { issue_kv(c + 2); CP_COMMIT(); }

        const int p = c % NSTG;
        const uint32_t sKf = sb + AKV + p * KVST;
        const uint32_t sVf = sKf + KT;

        float s[8][4];
#pragma unroll
        for (int i = 0; i < 8; i++)
#pragma unroll
            for (int j = 0; j < 4; j++) s[i][j] = 0.0f;

#pragma unroll
        for (int ks = 0; ks < 4; ks++) {
#pragma unroll
            for (int kp = 0; kp < 4; kp++) {
                uint32_t ro = (uint32_t)(kp * 16 + kb_row) * LDB + kb_kb + ks * 32;
                uint32_t r[4];
                ldm_x4(r, sKf + ro);
                uint32_t b0[2] = { r[0], r[1] }, b1[2] = { r[2], r[3] };
                mma16816h(s[2 * kp],     qh[ks], b0);
                mma16816h(s[2 * kp],     ql[ks], b0);
                mma16816h(s[2 * kp + 1], qh[ks], b1);
                mma16816h(s[2 * kp + 1], ql[ks], b1);
            }
        }

#pragma unroll
        for (int i = 0; i < 8; i++) {
            s[i][0] = exp2f(s[i][0]);
            s[i][1] = exp2f(s[i][1]);
            s[i][2] = exp2f(s[i][2]);
            s[i][3] = exp2f(s[i][3]);
            L0a += s[i][0]; L0b += s[i][1];
            L1a += s[i][2]; L1b += s[i][3];
        }

#pragma unroll
        for (int ks = 0; ks < 4; ks++) {
            uint32_t ph[4];
            ph[0] = packh2(s[2 * ks][0],     s[2 * ks][1]);
            ph[1] = packh2(s[2 * ks][2],     s[2 * ks][3]);
            ph[2] = packh2(s[2 * ks + 1][0], s[2 * ks + 1][1]);
            ph[3] = packh2(s[2 * ks + 1][2], s[2 * ks + 1][3]);

            const uint32_t vro = (uint32_t)(ks * 16 + vb_row) * LDB + vb_nb;
#pragma unroll
            for (int ntp = 0; ntp < 4; ntp++) {
                uint32_t r[4];
                ldm_x4_t(r, sVf + vro + ntp * 32);
                uint32_t v0[2] = { r[0], r[1] }, v1[2] = { r[2], r[3] };
                mma16816h(O[2 * ntp],     ph, v0);
                mma16816h(O[2 * ntp + 1], ph, v1);
            }
        }
    }

    float L0 = L0a + L0b, L1 = L1a + L1b;
    L0 += __shfl_xor_sync(0xFFFFFFFF, L0, 1);
    L0 += __shfl_xor_sync(0xFFFFFFFF, L0, 2);
    L1 += __shfl_xor_sync(0xFFFFFFFF, L1, 1);
    L1 += __shfl_xor_sync(0xFFFFFFFF, L1, 2);
    const float inv0 = 1.0f / L0, inv1 = 1.0f / L1;
    const float wmix = 1.0f / (1.0f + __expf(-qw[h]));

    const int r0 = q0 + w * 16 + (lane >> 2);
    const int c0 = (lane & 3) * 2;
    __half* oh0 = g_ah + base + (size_t)r0 * EMBED + c0;
    __half* ol0 = g_al + base + (size_t)r0 * EMBED + c0;
    __half* oh1 = g_ah + base + (size_t)(r0 + 8) * EMBED + c0;
    __half* ol1 = g_al + base + (size_t)(r0 + 8) * EMBED + c0;
#pragma unroll
    for (int nt = 0; nt < 8; nt++) {
        float ca = O[nt][0] * inv0, cb = O[nt][1] * inv0;
        float cc = O[nt][2] * inv1, cd = O[nt][3] * inv1;
        float ma = wmix * sinf(ca) + (1.0f - wmix) * ca;
        float mb = wmix * sinf(cb) + (1.0f - wmix) * cb;
        float mc = wmix * sinf(cc) + (1.0f - wmix) * cc;
        float md = wmix * sinf(cd) + (1.0f - wmix) * cd;
        uint32_t hh, ll;
        cvt_split2h(ma, mb, hh, ll);
        *(uint32_t*)(oh0 + nt * 8) = hh;
        *(uint32_t*)(ol0 + nt * 8) = ll;
        cvt_split2h(mc, md, hh, ll);
        *(uint32_t*)(oh1 + nt * 8) = hh;
        *(uint32_t*)(ol1 + nt * 8) = ll;
    }
}

// ---------------------------------------------------------------------------
extern "C" void kernel_launch(void* const* d_in, const int* in_sizes, int n_in,
                              void* d_out, int out_size)
{
    const float* x  = (const float*)d_in[0];
    const float* Wq = (const float*)d_in[1];
    const float* Wk = (const float*)d_in[2];
    const float* Wv = (const float*)d_in[3];
    const float* Wo = (const float*)d_in[4];
    const float* qw = (const float*)d_in[5];
    float* out = (float*)d_out;

    const int M = in_sizes[0] / EMBED;   // B*S = 4096
    const int S = SEQ;
    const int B = M / S;

    static bool attr_done = false;
    if (!attr_done) {
        cudaFuncSetAttribute(qkv_tc_kernel, cudaFuncAttributeMaxDynamicSharedMemorySize, SMEM_GEMM);
        cudaFuncSetAttribute(out_tc_kernel, cudaFuncAttributeMaxDynamicSharedMemorySize, SMEM_GEMM);
        cudaFuncSetAttribute(attn_tc_kernel, cudaFuncAttributeMaxDynamicSharedMemorySize, SMEM_ATTN);
        attr_done = true;
    }

    __half *p_xh, *p_xl, *p_wf;
    cudaGetSymbolAddress((void**)&p_xh, g_xh);
    cudaGetSymbolAddress((void**)&p_xl, g_xl);
    cudaGetSymbolAddress((void**)&p_wf, g_wf);

    // 0) Prep: x -> split fp16; weights -> single fp16
    {
        const int n4x = M * EMBED / 4;
        split_x_kernel<<<(n4x + 255) / 256, 256>>>(
            (const float4*)x, (uint2*)p_xh, (uint2*)p_xl, n4x);
        const int n4w = EMBED * EMBED / 4;
        dim3 gw((n4w + 255) / 256, 4);
        cvt_w_kernel<<<gw, 256>>>(
            (const float4*)Wq, (const float4*)Wk, (const float4*)Wv, (const float4*)Wo,
            (uint2*)p_wf, n4w);
    }

    // 1) Q,K,V projections (fp16 2-MMA GEMM)
    {
        dim3 grid(EMBED / TN, M / TM, 3);
        qkv_tc_kernel<<<grid, 512, SMEM_GEMM>>>();
    }
    // 2) Flash attention (fp16 datapath) + sin-mix
    {
        dim3 grid(S / 256, HEADS, B);
        attn_tc_kernel<<<grid, 512, SMEM_ATTN>>>(qw);
    }
    // 3) Output projection -> fp32 d_out
    {
        dim3 grid(EMBED / TN, M / TM, 1);
        out_tc_kernel<<<grid, 512, SMEM_GEMM>>>(out);
    }
}

// round 14
// speedup vs baseline: 2.5347x; 1.5008x over previous
#include <cuda_runtime.h>
#include <cuda_fp16.h>
#include <math.h>
#include <stdint.h>

#define EMBED 1024
#define HEADS 16
#define DK 64
#define SEQ 2048
#define MAXM 4096
#define NELEM (MAXM * EMBED)

// Persistent scratch (allocation-free rule: __device__ globals)
__device__ __half g_xf[NELEM];                    // x fp16
__device__ __half g_wf[4 * EMBED * EMBED];        // weights fp16
__device__ __half g_qf[NELEM];                    // Q fp16 (pre-scaled)
__device__ __half g_kf[NELEM];                    // K fp16
__device__ __half g_vf[NELEM];                    // V fp16
__device__ __half g_af[NELEM];                    // attn out fp16

// ===========================================================================
// Common helpers
// ===========================================================================
__device__ __forceinline__ uint32_t smem_u32(const void* p) {
    uint32_t a;
    asm("{ .reg .u64 t; cvta.to.shared.u64 t, %1; cvt.u32.u64 %0, t; }"
        : "=r"(a) : "l"(p));
    return a;
}

__device__ __forceinline__ void ldm_x4(uint32_t* r, uint32_t addr) {
    asm volatile("ldmatrix.sync.aligned.m8n8.x4.shared.b16 {%0,%1,%2,%3}, [%4];"
                 : "=r"(r[0]), "=r"(r[1]), "=r"(r[2]), "=r"(r[3]) : "r"(addr));
}

__device__ __forceinline__ void ldm_x4_t(uint32_t* r, uint32_t addr) {
    asm volatile("ldmatrix.sync.aligned.m8n8.x4.trans.shared.b16 {%0,%1,%2,%3}, [%4];"
                 : "=r"(r[0]), "=r"(r[1]), "=r"(r[2]), "=r"(r[3]) : "r"(addr));
}

__device__ __forceinline__ void mma16816h(float* d, const uint32_t* a, const uint32_t* b) {
    asm volatile(
        "mma.sync.aligned.m16n8k16.row.col.f32.f16.f16.f32 "
        "{%0,%1,%2,%3}, {%4,%5,%6,%7}, {%8,%9}, {%0,%1,%2,%3};"
        : "+f"(d[0]), "+f"(d[1]), "+f"(d[2]), "+f"(d[3])
        : "r"(a[0]), "r"(a[1]), "r"(a[2]), "r"(a[3]), "r"(b[0]), "r"(b[1]));
}

__device__ __forceinline__ void cp_async16(uint32_t dst, const void* src) {
    asm volatile("cp.async.cg.shared.global [%0], [%1], 16;"
                 :: "r"(dst), "l"(src) : "memory");
}
#define CP_COMMIT() asm volatile("cp.async.commit_group;" ::: "memory")
#define CP_WAIT(N)  asm volatile("cp.async.wait_group %0;" :: "n"(N) : "memory")

__device__ __forceinline__ uint32_t packh2(float a, float b) {
    __half2 h = __floats2half2_rn(a, b);
    return *reinterpret_cast<uint32_t*>(&h);
}

// ===========================================================================
// Prep kernels: fp32 -> fp16
// ===========================================================================
__global__ __launch_bounds__(256) void cvt_x_kernel(
    const float4* __restrict__ src, uint2* __restrict__ dst, int n4)
{
    int i = blockIdx.x * blockDim.x + threadIdx.x;
    if (i < n4) {
        float4 v = src[i];
        uint2 d;
        d.x = packh2(v.x, v.y);
        d.y = packh2(v.z, v.w);
        dst[i] = d;
    }
}

__global__ __launch_bounds__(256) void cvt_w_kernel(
    const float4* __restrict__ w0, const float4* __restrict__ w1,
    const float4* __restrict__ w2, const float4* __restrict__ w3,
    uint2* __restrict__ dst, int n4)
{
    const int z = blockIdx.y;
    const float4* src = (z == 0) ? w0 : (z == 1) ? w1 : (z == 2) ? w2 : w3;
    int i = blockIdx.x * blockDim.x + threadIdx.x;
    if (i < n4) {
        float4 v = src[i];
        uint2 d;
        d.x = packh2(v.x, v.y);
        d.y = packh2(v.z, v.w);
        dst[(size_t)z * n4 + i] = d;
    }
}

// ===========================================================================
// GEMM: C[m,n] = sum_k A[m,k]*B[n,k]  (NT), plain fp16, 1 MMA per product.
// CTA 128x128, 512 threads (16 warps 4x4, warp tile 32x32), K-chunk 64,
// 3-stage cp.async pipeline. Epilogue mode: 0=fp32, 3=fp16.
// ===========================================================================
#define TM 128
#define TN 128
#define KCH 64
#define LDB 144
#define GT (128 * LDB)             // 18432 per 128x64 fp16 tile
#define GSTAGE (2 * GT)            // A, B = 36864
#define NSTG 3
#define SMEM_GEMM (NSTG * GSTAGE)  // 110592

__device__ __forceinline__ void gemm_f16_body(
    const __half* __restrict__ Af, const __half* __restrict__ Bf,
    float* __restrict__ Cf, __half* __restrict__ Ch,
    float scale, int mode)
{
    extern __shared__ char smem[];
    const uint32_t sbase = smem_u32(smem);
    const int tid  = threadIdx.x;
    const int lane = tid & 31;
    const int wid  = tid >> 5;
    const int wm   = wid & 3;
    const int wn   = wid >> 2;
    const int m0 = blockIdx.y * TM;
    const int n0 = blockIdx.x * TN;

    float acc[2][4][4];
#pragma unroll
    for (int i = 0; i < 2; i++)
#pragma unroll
        for (int j = 0; j < 4; j++)
#pragma unroll
            for (int r = 0; r < 4; r++) acc[i][j][r] = 0.0f;

    int lrow[2], lu4[2];
#pragma unroll
    for (int i = 0; i < 2; i++) {
        int idx = tid + i * 512;
        lrow[i] = idx >> 3;
        lu4[i]  = idx & 7;
    }

    const __half* Ab = Af + (size_t)m0 * EMBED;
    const __half* Bb = Bf + (size_t)n0 * EMBED;

    const int NCHUNK = EMBED / KCH;

    auto issue = [&](int c) {
        const uint32_t stu = sbase + (c % NSTG) * GSTAGE;
        const int koff = c * KCH;
#pragma unroll
        for (int i = 0; i < 2; i++) {
            size_t off = (size_t)lrow[i] * EMBED + koff + lu4[i] * 8;
            uint32_t bo = lrow[i] * LDB + lu4[i] * 16;
            cp_async16(stu + 0 * GT + bo, Ab + off);
            cp_async16(stu + 1 * GT + bo, Bb + off);
        }
    };

    issue(0); CP_COMMIT();
    issue(1); CP_COMMIT();

    const int a_row = wm * 32 + (lane & 15);
    const int a_kb  = (lane >> 4) * 16;
    const int b_row = wn * 32 + ((lane >> 4) & 1) * 8 + (lane & 7);
    const int b_kb  = ((lane >> 3) & 1) * 16;

    for (int c = 0; c < NCHUNK; ++c) {
        CP_WAIT(1);
        __syncthreads();
        if (c + 2 < NCHUNK) { issue(c + 2); CP_COMMIT(); }

        const int p = c % NSTG;
        const uint32_t sA = sbase + p * GSTAGE;
        const uint32_t sB = sA + GT;

#pragma unroll
        for (int ks = 0; ks < 4; ++ks) {
            uint32_t a[2][4];
            uint32_t bh[4][2];

            const uint32_t akoff = ks * 32 + a_kb;
#pragma unroll
            for (int mi = 0; mi < 2; mi++) {
                uint32_t ro = (uint32_t)(a_row + mi * 16) * LDB + akoff;
                ldm_x4(a[mi], sA + ro);
            }
            const uint32_t bkoff = ks * 32 + b_kb;
#pragma unroll
            for (int np = 0; np < 2; np++) {
                uint32_t ro = (uint32_t)(b_row + np * 16) * LDB + bkoff;
                uint32_t r[4];
                ldm_x4(r, sB + ro);
                bh[np * 2][0] = r[0]; bh[np * 2][1] = r[1];
                bh[np * 2 + 1][0] = r[2]; bh[np * 2 + 1][1] = r[3];
            }

#pragma unroll
            for (int mi = 0; mi < 2; mi++)
#pragma unroll
                for (int ni = 0; ni < 4; ni++)
                    mma16816h(acc[mi][ni], a[mi], bh[ni]);
        }
    }

    const int er = lane >> 2;
    const int ec = (lane & 3) * 2;
#pragma unroll
    for (int mi = 0; mi < 2; mi++) {
#pragma unroll
        for (int ni = 0; ni < 4; ni++) {
            int row = m0 + wm * 32 + mi * 16 + er;
            int col = n0 + wn * 32 + ni * 8 + ec;
            float a0 = acc[mi][ni][0] * scale, a1 = acc[mi][ni][1] * scale;
            float a2 = acc[mi][ni][2] * scale, a3 = acc[mi][ni][3] * scale;
            if (mode == 0) {
                *(float2*)(Cf + (size_t)row * EMBED + col) = make_float2(a0, a1);
                *(float2*)(Cf + (size_t)(row + 8) * EMBED + col) = make_float2(a2, a3);
            } else {
                *(uint32_t*)(Ch + (size_t)row * EMBED + col) = packh2(a0, a1);
                *(uint32_t*)(Ch + (size_t)(row + 8) * EMBED + col) = packh2(a2, a3);
            }
        }
    }
}

__global__ __launch_bounds__(512, 1) void qkv_tc_kernel()
{
    const int z = blockIdx.z;
    const __half* Bf = g_wf + (size_t)z * EMBED * EMBED;
    if (z == 0)       // Q: scale folds 1/sqrt(DK) * log2(e)
        gemm_f16_body(g_xf, Bf, nullptr, g_qf, 0.125f * 1.4426950408889634f, 3);
    else if (z == 1)
        gemm_f16_body(g_xf, Bf, nullptr, g_kf, 1.0f, 3);
    else
        gemm_f16_body(g_xf, Bf, nullptr, g_vf, 1.0f, 3);
}

__global__ __launch_bounds__(512, 1) void out_tc_kernel(float* __restrict__ out)
{
    gemm_f16_body(g_af, g_wf + (size_t)3 * EMBED * EMBED, out, nullptr, 1.0f, 0);
}

// ===========================================================================
// Tensor-core flash attention, plain fp16 datapath:
//   scores = Q . K -> 1 MMA;  O += P . V -> 1 MMA
// Shift-free base-2 softmax. 512 threads, 256 q-rows, 64-key chunks.
// ===========================================================================
#define KT (64 * LDB)
#define QT (256 * LDB)
#define AQF 0
#define AKV QT
#define KVST (2 * KT)
#define SMEM_ATTN (QT + NSTG * KVST)   // 92160

__global__ __launch_bounds__(512, 1) void attn_tc_kernel(
    const float* __restrict__ qw)
{
    extern __shared__ char smem[];
    const uint32_t sb = smem_u32(smem);
    const int tid  = threadIdx.x;
    const int lane = tid & 31;
    const int w    = tid >> 5;
    const int h = blockIdx.y;
    const int b = blockIdx.z;
    const int q0 = blockIdx.x * 256;

    const size_t base = (size_t)b * SEQ * EMBED + (size_t)h * DK;

    const int krow = tid >> 3;
    const int ku4  = tid & 7;

    auto issue_kv = [&](int c) {
        const uint32_t stu = sb + AKV + (c % NSTG) * KVST;
        size_t off = base + (size_t)(c * 64 + krow) * EMBED + ku4 * 8;
        uint32_t bo = krow * LDB + ku4 * 16;
        cp_async16(stu + 0 * KT + bo, g_kf + off);
        cp_async16(stu + 1 * KT + bo, g_vf + off);
    };

    issue_kv(0); CP_COMMIT();
    issue_kv(1); CP_COMMIT();

    // ---- copy fp16 Q tile into SMEM ----
    {
        const __half* Qf = g_qf + base + (size_t)q0 * EMBED;
#pragma unroll
        for (int i = 0; i < 4; i++) {
            int idx = i * 512 + tid;
            int row = idx >> 3, u4 = idx & 7;
            size_t off = (size_t)row * EMBED + u4 * 8;
            uint32_t bo = row * LDB + u4 * 16;
            *(uint4*)(smem + AQF + bo) = *(const uint4*)(Qf + off);
        }
    }
    __syncthreads();

    // ---- Q fragments, register resident ----
    uint32_t qf[4][4];
    {
        const uint32_t aoff = (uint32_t)(w * 16 + (lane & 15)) * LDB + (lane >> 4) * 16;
#pragma unroll
        for (int ks = 0; ks < 4; ks++)
            ldm_x4(qf[ks], sb + AQF + aoff + ks * 32);
    }

    float O[8][4];
#pragma unroll
    for (int i = 0; i < 8; i++)
#pragma unroll
        for (int j = 0; j < 4; j++) O[i][j] = 0.0f;
    float L0a = 0.0f, L0b = 0.0f, L1a = 0.0f, L1b = 0.0f;

    const uint32_t kb_row = ((lane >> 4) & 1) * 8 + (lane & 7);
    const uint32_t kb_kb  = ((lane >> 3) & 1) * 16;
    const uint32_t vb_row = ((lane >> 3) & 1) * 8 + (lane & 7);
    const uint32_t vb_nb  = (lane >> 4) * 16;

    const int NCH = SEQ / 64;   // 32
    for (int c = 0; c < NCH; ++c) {
        CP_WAIT(1);
        __syncthreads();
        if (c + 2 < NCH) { issue_kv(c + 2); CP_COMMIT(); }

        const int p = c % NSTG;
        const uint32_t sKf = sb + AKV + p * KVST;
        const uint32_t sVf = sKf + KT;

        // ---- scores: 1 fp16 MMA per product ----
        float s[8][4];
#pragma unroll
        for (int i = 0; i < 8; i++)
#pragma unroll
            for (int j = 0; j < 4; j++) s[i][j] = 0.0f;

#pragma unroll
        for (int ks = 0; ks < 4; ks++) {
#pragma unroll
            for (int kp = 0; kp < 4; kp++) {
                uint32_t ro = (uint32_t)(kp * 16 + kb_row) * LDB + kb_kb + ks * 32;
                uint32_t r[4];
                ldm_x4(r, sKf + ro);
                uint32_t b0[2] = { r[0], r[1] }, b1[2] = { r[2], r[3] };
                mma16816h(s[2 * kp],     qf[ks], b0);
                mma16816h(s[2 * kp + 1], qf[ks], b1);
            }
        }

        // ---- shift-free softmax ----
#pragma unroll
        for (int i = 0; i < 8; i++) {
            s[i][0] = exp2f(s[i][0]);
            s[i][1] = exp2f(s[i][1]);
            s[i][2] = exp2f(s[i][2]);
            s[i][3] = exp2f(s[i][3]);
            L0a += s[i][0]; L0b += s[i][1];
            L1a += s[i][2]; L1b += s[i][3];
        }

        // ---- O += P . V ----
#pragma unroll
        for (int ks = 0; ks < 4; ks++) {
            uint32_t ph[4];
            ph[0] = packh2(s[2 * ks][0],     s[2 * ks][1]);
            ph[1] = packh2(s[2 * ks][2],     s[2 * ks][3]);
            ph[2] = packh2(s[2 * ks + 1][0], s[2 * ks + 1][1]);
            ph[3] = packh2(s[2 * ks + 1][2], s[2 * ks + 1][3]);

            const uint32_t vro = (uint32_t)(ks * 16 + vb_row) * LDB + vb_nb;
#pragma unroll
            for (int ntp = 0; ntp < 4; ntp++) {
                uint32_t r[4];
                ldm_x4_t(r, sVf + vro + ntp * 32);
                uint32_t v0[2] = { r[0], r[1] }, v1[2] = { r[2], r[3] };
                mma16816h(O[2 * ntp],     ph, v0);
                mma16816h(O[2 * ntp + 1], ph, v1);
            }
        }
    }

    // ---- finalize: reduce L, normalize, sin-mix, write fp16 ----
    float L0 = L0a + L0b, L1 = L1a + L1b;
    L0 += __shfl_xor_sync(0xFFFFFFFF, L0, 1);
    L0 += __shfl_xor_sync(0xFFFFFFFF, L0, 2);
    L1 += __shfl_xor_sync(0xFFFFFFFF, L1, 1);
    L1 += __shfl_xor_sync(0xFFFFFFFF, L1, 2);
    const float inv0 = 1.0f / L0, inv1 = 1.0f / L1;
    const float wmix = 1.0f / (1.0f + __expf(-qw[h]));

    const int r0 = q0 + w * 16 + (lane >> 2);
    const int c0 = (lane & 3) * 2;
    __half* o0 = g_af + base + (size_t)r0 * EMBED + c0;
    __half* o1 = g_af + base + (size_t)(r0 + 8) * EMBED + c0;
#pragma unroll
    for (int nt = 0; nt < 8; nt++) {
        float ca = O[nt][0] * inv0, cb = O[nt][1] * inv0;
        float cc = O[nt][2] * inv1, cd = O[nt][3] * inv1;
        float ma = wmix * sinf(ca) + (1.0f - wmix) * ca;
        float mb = wmix * sinf(cb) + (1.0f - wmix) * cb;
        float mc = wmix * sinf(cc) + (1.0f - wmix) * cc;
        float md = wmix * sinf(cd) + (1.0f - wmix) * cd;
        *(uint32_t*)(o0 + nt * 8) = packh2(ma, mb);
        *(uint32_t*)(o1 + nt * 8) = packh2(mc, md);
    }
}

// ---------------------------------------------------------------------------
extern "C" void kernel_launch(void* const* d_in, const int* in_sizes, int n_in,
                              void* d_out, int out_size)
{
    const float* x  = (const float*)d_in[0];
    const float* Wq = (const float*)d_in[1];
    const float* Wk = (const float*)d_in[2];
    const float* Wv = (const float*)d_in[3];
    const float* Wo = (const float*)d_in[4];
    const float* qw = (const float*)d_in[5];
    float* out = (float*)d_out;

    const int M = in_sizes[0] / EMBED;   // B*S = 4096
    const int S = SEQ;
    const int B = M / S;

    static bool attr_done = false;
    if (!attr_done) {
        cudaFuncSetAttribute(qkv_tc_kernel, cudaFuncAttributeMaxDynamicSharedMemorySize, SMEM_GEMM);
        cudaFuncSetAttribute(out_tc_kernel, cudaFuncAttributeMaxDynamicSharedMemorySize, SMEM_GEMM);
        cudaFuncSetAttribute(attn_tc_kernel, cudaFuncAttributeMaxDynamicSharedMemorySize, SMEM_ATTN);
        attr_done = true;
    }

    __half *p_xf, *p_wf;
    cudaGetSymbolAddress((void**)&p_xf, g_xf);
    cudaGetSymbolAddress((void**)&p_wf, g_wf);

    // 0) Prep: x, weights -> fp16
    {
        const int n4x = M * EMBED / 4;
        cvt_x_kernel<<<(n4x + 255) / 256, 256>>>(
            (const float4*)x, (uint2*)p_xf, n4x);
        const int n4w = EMBED * EMBED / 4;
        dim3 gw((n4w + 255) / 256, 4);
        cvt_w_kernel<<<gw, 256>>>(
            (const float4*)Wq, (const float4*)Wk, (const float4*)Wv, (const float4*)Wo,
            (uint2*)p_wf, n4w);
    }

    // 1) Q,K,V projections (fp16 1-MMA GEMM)
    {
        dim3 grid(EMBED / TN, M / TM, 3);
        qkv_tc_kernel<<<grid, 512, SMEM_GEMM>>>();
    }
    // 2) Flash attention (fp16 datapath) + sin-mix
    {
        dim3 grid(S / 256, HEADS, B);
        attn_tc_kernel<<<grid, 512, SMEM_ATTN>>>(qw);
    }
    // 3) Output projection -> fp32 d_out
    {
        dim3 grid(EMBED / TN, M / TM, 1);
        out_tc_kernel<<<grid, 512, SMEM_GEMM>>>(out);
    }
}